// round 1
// baseline (speedup 1.0000x reference)
#include <cuda_runtime.h>
#include <math.h>

#define DM     1024
#define NH     16
#define DH     64
#define BATCH  4
#define SEQ    2048
#define TOKENS (BATCH * SEQ)

// Scratch (static device memory — no allocations allowed)
__device__ float g_Q[TOKENS * DM];
__device__ float g_K[TOKENS * DM];
__device__ float g_V[TOKENS * DM];
__device__ float g_att[TOKENS * DM];

// ---------------------------------------------------------------------------
// NT SGEMM: C[M,N] = A[M,K] @ B[N,K]^T + bias[N]
// BM=BN=64, BK=16, 256 threads, 4x4 microtile per thread.
// MODE 0: A = x, scatter output into g_Q/g_K/g_V as [B,H,S,DH]
// MODE 1: A = g_att, plain row-major output into C
// ---------------------------------------------------------------------------
template <int MODE>
__global__ void __launch_bounds__(256) gemm_nt_kernel(
    const float* __restrict__ A_in, const float* __restrict__ B,
    const float* __restrict__ bias, float* __restrict__ C,
    int M, int N, int K)
{
    __shared__ float As[16][68];
    __shared__ float Bs[16][68];

    const float* A = (MODE == 1) ? (const float*)g_att : A_in;

    const int t  = threadIdx.x;
    const int tx = t & 15, ty = t >> 4;
    const int m0 = blockIdx.y << 6;
    const int n0 = blockIdx.x << 6;
    const int lm = t >> 2;          // 0..63
    const int lk = (t & 3) << 2;    // 0,4,8,12

    const float* Ap = A + (size_t)(m0 + lm) * K + lk;
    const float* Bp = B + (size_t)(n0 + lm) * K + lk;

    float acc[4][4] = {};

    for (int k0 = 0; k0 < K; k0 += 16) {
        float4 va = *(const float4*)(Ap + k0);
        float4 vb = *(const float4*)(Bp + k0);
        As[lk + 0][lm] = va.x; As[lk + 1][lm] = va.y;
        As[lk + 2][lm] = va.z; As[lk + 3][lm] = va.w;
        Bs[lk + 0][lm] = vb.x; Bs[lk + 1][lm] = vb.y;
        Bs[lk + 2][lm] = vb.z; Bs[lk + 3][lm] = vb.w;
        __syncthreads();
#pragma unroll
        for (int k = 0; k < 16; k++) {
            float4 a = *(const float4*)(&As[k][ty << 2]);
            float4 b = *(const float4*)(&Bs[k][tx << 2]);
            float av[4] = {a.x, a.y, a.z, a.w};
            float bv[4] = {b.x, b.y, b.z, b.w};
#pragma unroll
            for (int i = 0; i < 4; i++)
#pragma unroll
                for (int j = 0; j < 4; j++)
                    acc[i][j] += av[i] * bv[j];
        }
        __syncthreads();
    }

    float4 bvec = *(const float4*)(bias + n0 + (tx << 2));
    float bb[4] = {bvec.x, bvec.y, bvec.z, bvec.w};

    if (MODE == 0) {
        // n0 is 64-aligned: the whole 64-wide tile belongs to one (which, head)
        const int which = n0 >> 10;            // 0=Q, 1=K, 2=V
        const int head  = (n0 & 1023) >> 6;
        float* dst = (which == 0) ? g_Q : (which == 1) ? g_K : g_V;
#pragma unroll
        for (int i = 0; i < 4; i++) {
            const int tok = m0 + (ty << 2) + i;
            const int b   = tok >> 11;         // / SEQ
            const int s   = tok & 2047;        // % SEQ
            float4 o;
            o.x = acc[i][0] + bb[0]; o.y = acc[i][1] + bb[1];
            o.z = acc[i][2] + bb[2]; o.w = acc[i][3] + bb[3];
            *(float4*)(&dst[(((size_t)(b * NH + head)) * SEQ + s) * DH + (tx << 2)]) = o;
        }
    } else {
#pragma unroll
        for (int i = 0; i < 4; i++) {
            float4 o;
            o.x = acc[i][0] + bb[0]; o.y = acc[i][1] + bb[1];
            o.z = acc[i][2] + bb[2]; o.w = acc[i][3] + bb[3];
            *(float4*)(&C[(size_t)(m0 + (ty << 2) + i) * N + n0 + (tx << 2)]) = o;
        }
    }
}

// ---------------------------------------------------------------------------
// Causal flash attention, fp32. 64 q-rows x 64 k-rows per tile, dh=64.
// 256 threads (ty 0..15, tx 0..15), 4x4 microtiles, online softmax with
// shfl_xor reductions across the 16-lane tx group (rows live in one warp half).
// Output written in [B,S,D] layout into g_att.
// ---------------------------------------------------------------------------
#define FLASH_SMEM (4 * 64 * 68 * 4)

__global__ void __launch_bounds__(256) flash_kernel()
{
    extern __shared__ float smem[];
    float (*Qs)[68] = (float(*)[68])(smem);               // Q^T : [d][m]
    float (*Ks)[68] = (float(*)[68])(smem + 64 * 68);     // K^T : [d][n]
    float (*Vs)[68] = (float(*)[68])(smem + 2 * 64 * 68); // V   : [k][d]
    float (*Ps)[68] = (float(*)[68])(smem + 3 * 64 * 68); // P   : [q][k]

    const int t  = threadIdx.x;
    const int tx = t & 15, ty = t >> 4;
    const int qt = blockIdx.x;      // q tile (0..31)
    const int h  = blockIdx.y;
    const int b  = blockIdx.z;
    const int q0 = qt << 6;

    const size_t base = ((size_t)(b * NH + h)) * SEQ * DH;
    const float* Qp = g_Q + base;
    const float* Kp = g_K + base;
    const float* Vp = g_V + base;

    const int lm = t >> 2;          // 0..63
    const int ld = (t & 3) << 2;    // 0,4,8,12

    // Load Q tile transposed (stays resident all iterations)
#pragma unroll
    for (int c = 0; c < 4; c++) {
        const int d = c * 16 + ld;
        float4 v = *(const float4*)(Qp + (size_t)(q0 + lm) * DH + d);
        Qs[d + 0][lm] = v.x; Qs[d + 1][lm] = v.y;
        Qs[d + 2][lm] = v.z; Qs[d + 3][lm] = v.w;
    }

    float o[4][4] = {};
    float mrow[4] = {-1e30f, -1e30f, -1e30f, -1e30f};
    float lrow[4] = {};

    for (int kt = 0; kt <= qt; kt++) {
        const int k0 = kt << 6;
        __syncthreads();  // prev PV done before overwriting Ks/Vs
#pragma unroll
        for (int c = 0; c < 4; c++) {
            const int d = c * 16 + ld;
            float4 v = *(const float4*)(Kp + (size_t)(k0 + lm) * DH + d);
            Ks[d + 0][lm] = v.x; Ks[d + 1][lm] = v.y;
            Ks[d + 2][lm] = v.z; Ks[d + 3][lm] = v.w;
            float4 w = *(const float4*)(Vp + (size_t)(k0 + lm) * DH + d);
            *(float4*)(&Vs[lm][d]) = w;
        }
        __syncthreads();

        // S = Q @ K^T
        float s[4][4] = {};
#pragma unroll 8
        for (int d = 0; d < 64; d++) {
            float4 a  = *(const float4*)(&Qs[d][ty << 2]);
            float4 bq = *(const float4*)(&Ks[d][tx << 2]);
            float av[4] = {a.x, a.y, a.z, a.w};
            float bv[4] = {bq.x, bq.y, bq.z, bq.w};
#pragma unroll
            for (int i = 0; i < 4; i++)
#pragma unroll
                for (int j = 0; j < 4; j++)
                    s[i][j] += av[i] * bv[j];
        }

        // scale + causal mask
#pragma unroll
        for (int i = 0; i < 4; i++) {
            const int qi = q0 + (ty << 2) + i;
#pragma unroll
            for (int j = 0; j < 4; j++) {
                const int kj = k0 + (tx << 2) + j;
                s[i][j] = (kj <= qi) ? s[i][j] * 0.125f : -1e30f;
            }
        }

        // online softmax (row spread over 16 tx lanes of one warp half)
#pragma unroll
        for (int i = 0; i < 4; i++) {
            float rmax = fmaxf(fmaxf(s[i][0], s[i][1]), fmaxf(s[i][2], s[i][3]));
#pragma unroll
            for (int off = 8; off; off >>= 1)
                rmax = fmaxf(rmax, __shfl_xor_sync(0xffffffffu, rmax, off));
            const float mnew  = fmaxf(mrow[i], rmax);
            const float alpha = __expf(mrow[i] - mnew);
            const float p0 = __expf(s[i][0] - mnew);
            const float p1 = __expf(s[i][1] - mnew);
            const float p2 = __expf(s[i][2] - mnew);
            const float p3 = __expf(s[i][3] - mnew);
            float rsum = (p0 + p1) + (p2 + p3);
#pragma unroll
            for (int off = 8; off; off >>= 1)
                rsum += __shfl_xor_sync(0xffffffffu, rsum, off);
            lrow[i] = lrow[i] * alpha + rsum;
            mrow[i] = mnew;
            o[i][0] *= alpha; o[i][1] *= alpha; o[i][2] *= alpha; o[i][3] *= alpha;
            *(float4*)(&Ps[(ty << 2) + i][tx << 2]) = make_float4(p0, p1, p2, p3);
        }
        __syncthreads();

        // O += P @ V
#pragma unroll 4
        for (int kk = 0; kk < 64; kk += 4) {
            float4 a0 = *(const float4*)(&Ps[(ty << 2) + 0][kk]);
            float4 a1 = *(const float4*)(&Ps[(ty << 2) + 1][kk]);
            float4 a2 = *(const float4*)(&Ps[(ty << 2) + 2][kk]);
            float4 a3 = *(const float4*)(&Ps[(ty << 2) + 3][kk]);
            float A0[4] = {a0.x, a0.y, a0.z, a0.w};
            float A1[4] = {a1.x, a1.y, a1.z, a1.w};
            float A2[4] = {a2.x, a2.y, a2.z, a2.w};
            float A3[4] = {a3.x, a3.y, a3.z, a3.w};
#pragma unroll
            for (int r = 0; r < 4; r++) {
                float4 bv = *(const float4*)(&Vs[kk + r][tx << 2]);
                float bb[4] = {bv.x, bv.y, bv.z, bv.w};
#pragma unroll
                for (int j = 0; j < 4; j++) {
                    o[0][j] += A0[r] * bb[j];
                    o[1][j] += A1[r] * bb[j];
                    o[2][j] += A2[r] * bb[j];
                    o[3][j] += A3[r] * bb[j];
                }
            }
        }
    }

    // normalize and write out in [B,S,D] layout
#pragma unroll
    for (int i = 0; i < 4; i++) {
        const float inv = 1.0f / lrow[i];
        const int tok = b * SEQ + q0 + (ty << 2) + i;
        float4 ov = make_float4(o[i][0] * inv, o[i][1] * inv,
                                o[i][2] * inv, o[i][3] * inv);
        *(float4*)(&g_att[(size_t)tok * DM + h * DH + (tx << 2)]) = ov;
    }
}

// ---------------------------------------------------------------------------
extern "C" void kernel_launch(void* const* d_in, const int* in_sizes, int n_in,
                              void* d_out, int out_size)
{
    (void)in_sizes; (void)n_in; (void)out_size;
    const float* x    = (const float*)d_in[0];
    const float* Wqkv = (const float*)d_in[1];
    const float* bqkv = (const float*)d_in[2];
    const float* Wo   = (const float*)d_in[3];
    const float* bo   = (const float*)d_in[4];
    float* out = (float*)d_out;

    cudaFuncSetAttribute(flash_kernel,
                         cudaFuncAttributeMaxDynamicSharedMemorySize, FLASH_SMEM);

    // QKV projection: [8192,1024] @ [3072,1024]^T -> scatter to Q/K/V
    gemm_nt_kernel<0><<<dim3(3 * DM / 64, TOKENS / 64), 256>>>(
        x, Wqkv, bqkv, nullptr, TOKENS, 3 * DM, DM);

    // Causal flash attention -> g_att [B,S,D]
    flash_kernel<<<dim3(SEQ / 64, NH, BATCH), 256, FLASH_SMEM>>>();

    // Output projection: g_att @ Wo^T + bo -> d_out
    gemm_nt_kernel<1><<<dim3(DM / 64, TOKENS / 64), 256>>>(
        nullptr, Wo, bo, out, TOKENS, DM, DM);
}

// round 3
// speedup vs baseline: 1.6521x; 1.6521x over previous
#include <cuda_runtime.h>
#include <cuda_bf16.h>
#include <math.h>

#define DM     1024
#define NH     16
#define DH     64
#define BATCH  4
#define SEQ    2048
#define TOKENS (BATCH * SEQ)

// ---------------------------------------------------------------------------
// Scratch (static device memory — no allocations allowed)
// ---------------------------------------------------------------------------
__device__ float g_Q[TOKENS * DM];
__device__ float g_K[TOKENS * DM];
__device__ float g_V[TOKENS * DM];
__device__ float g_att[TOKENS * DM];

__device__ __align__(16) __nv_bfloat16 g_xhi[TOKENS * DM];
__device__ __align__(16) __nv_bfloat16 g_xlo[TOKENS * DM];
__device__ __align__(16) __nv_bfloat16 g_wqkv_hi[3 * DM * DM];
__device__ __align__(16) __nv_bfloat16 g_wqkv_lo[3 * DM * DM];
__device__ __align__(16) __nv_bfloat16 g_wo_hi[DM * DM];
__device__ __align__(16) __nv_bfloat16 g_wo_lo[DM * DM];
__device__ __align__(16) __nv_bfloat16 g_ahi[TOKENS * DM];
__device__ __align__(16) __nv_bfloat16 g_alo[TOKENS * DM];

// ---------------------------------------------------------------------------
// warp-MMA helpers (compute_103-safe: ldmatrix + mma.sync HMMA path)
// ---------------------------------------------------------------------------
__device__ __forceinline__ unsigned smem_to_u32(const void* p) {
    unsigned a;
    asm("{ .reg .u64 t; cvta.to.shared.u64 t, %1; cvt.u32.u64 %0, t; }"
        : "=r"(a) : "l"(p));
    return a;
}

__device__ __forceinline__ void ldsm_x4(unsigned& r0, unsigned& r1,
                                        unsigned& r2, unsigned& r3,
                                        unsigned addr) {
    asm volatile("ldmatrix.sync.aligned.m8n8.x4.shared.b16 {%0,%1,%2,%3}, [%4];"
                 : "=r"(r0), "=r"(r1), "=r"(r2), "=r"(r3) : "r"(addr));
}

__device__ __forceinline__ void mma16816(float* d, const unsigned* a,
                                         const unsigned* b) {
    asm volatile(
        "mma.sync.aligned.m16n8k16.row.col.f32.bf16.bf16.f32 "
        "{%0,%1,%2,%3}, {%4,%5,%6,%7}, {%8,%9}, {%0,%1,%2,%3};"
        : "+f"(d[0]), "+f"(d[1]), "+f"(d[2]), "+f"(d[3])
        : "r"(a[0]), "r"(a[1]), "r"(a[2]), "r"(a[3]), "r"(b[0]), "r"(b[1]));
}

// ---------------------------------------------------------------------------
// fp32 -> bf16 hi/lo split. mode: 0=x, 1=W_qkv, 2=W_o, 3=g_att
// ---------------------------------------------------------------------------
__global__ void __launch_bounds__(256) split_kernel(
    const float* __restrict__ src, int mode, int n4)
{
    int i = blockIdx.x * blockDim.x + threadIdx.x;
    if (i >= n4) return;
    float4 v = (mode == 3) ? ((const float4*)g_att)[i] : ((const float4*)src)[i];
    __nv_bfloat16 *hp, *lp;
    if (mode == 0)      { hp = g_xhi;     lp = g_xlo; }
    else if (mode == 1) { hp = g_wqkv_hi; lp = g_wqkv_lo; }
    else if (mode == 2) { hp = g_wo_hi;   lp = g_wo_lo; }
    else                { hp = g_ahi;     lp = g_alo; }

    float f[4] = {v.x, v.y, v.z, v.w};
    __nv_bfloat16 h[4], l[4];
#pragma unroll
    for (int j = 0; j < 4; j++) {
        h[j] = __float2bfloat16(f[j]);
        l[j] = __float2bfloat16(f[j] - __bfloat162float(h[j]));
    }
    ((__nv_bfloat162*)hp)[2 * i]     = __halves2bfloat162(h[0], h[1]);
    ((__nv_bfloat162*)hp)[2 * i + 1] = __halves2bfloat162(h[2], h[3]);
    ((__nv_bfloat162*)lp)[2 * i]     = __halves2bfloat162(l[0], l[1]);
    ((__nv_bfloat162*)lp)[2 * i + 1] = __halves2bfloat162(l[2], l[3]);
}

// ---------------------------------------------------------------------------
// Tensor-core GEMM (mma.sync bf16, 3-term split), NT:
//   C[M,N] = A[M,K] @ B[N,K]^T + bias[N],  K = 1024
// CTA: 128x128 tile, 8 warps (2x4), each warp 64x32. BK=32.
// MODE 0: A=x(hi/lo), B=W_qkv(hi/lo) -> scatter to g_Q/g_K/g_V [B,H,S,DH]
// MODE 1: A=att(hi/lo), B=W_o(hi/lo) -> row-major Cout
// ---------------------------------------------------------------------------
#define SSTRIDE 40   // bf16 elements per smem row (80 B, 16B-aligned, LDSM conflict-free)

template <int MODE>
__global__ void __launch_bounds__(256, 2) tc_gemm_kernel(
    const float* __restrict__ bias, float* __restrict__ Cout)
{
    __shared__ __align__(16) __nv_bfloat16 sA[2][128][SSTRIDE]; // [hi/lo]
    __shared__ __align__(16) __nv_bfloat16 sB[2][128][SSTRIDE];

    const int tid  = threadIdx.x;
    const int lane = tid & 31;
    const int wid  = tid >> 5;
    const int n0 = blockIdx.x << 7;
    const int m0 = blockIdx.y << 7;

    const int warp_m = (wid & 1) << 6;   // 0 or 64
    const int warp_n = (wid >> 1) << 5;  // 0,32,64,96

    const __nv_bfloat16* Ahi = (MODE == 0) ? g_xhi : g_ahi;
    const __nv_bfloat16* Alo = (MODE == 0) ? g_xlo : g_alo;
    const __nv_bfloat16* Bhi = (MODE == 0) ? g_wqkv_hi : g_wo_hi;
    const __nv_bfloat16* Blo = (MODE == 0) ? g_wqkv_lo : g_wo_lo;

    // staging assignment: 64 threads per tile {Ahi,Alo,Bhi,Blo}
    const int tl   = tid >> 6;
    const int t6   = tid & 63;
    const int quad = t6 & 3;        // 16B chunk within 64B row
    const int rb   = t6 >> 2;       // 0..15
    const __nv_bfloat16* gsrc = (tl == 0) ? Ahi : (tl == 1) ? Alo
                              : (tl == 2) ? Bhi : Blo;
    const int rowoff = (tl < 2) ? m0 : n0;
    __nv_bfloat16* sdst = (tl == 0) ? &sA[0][0][0] : (tl == 1) ? &sA[1][0][0]
                        : (tl == 2) ? &sB[0][0][0] : &sB[1][0][0];
    const __nv_bfloat16* gp = gsrc + (size_t)(rowoff + rb) * DM + quad * 8;

    // ldmatrix lane base addresses
    const unsigned sA_u = smem_to_u32(&sA[0][0][0]);
    const unsigned sB_u = smem_to_u32(&sB[0][0][0]);
    const unsigned aHi = sA_u + (warp_m + (lane & 15)) * (SSTRIDE * 2)
                              + ((lane >> 4) << 4);
    const unsigned aLo = aHi + 128 * SSTRIDE * 2;
    const unsigned bRow = warp_n + ((lane >> 4) << 3) + (lane & 7);
    const unsigned bHi = sB_u + bRow * (SSTRIDE * 2) + (((lane >> 3) & 1) << 4);
    const unsigned bLo = bHi + 128 * SSTRIDE * 2;

    float acc[4][4][4] = {};

    for (int kc = 0; kc < DM; kc += 32) {
        __syncthreads();
#pragma unroll
        for (int p = 0; p < 8; p++) {
            const int row = rb + p * 16;
            uint4 v = *(const uint4*)(gp + (size_t)p * 16 * DM + kc);
            *(uint4*)((char*)sdst + row * (SSTRIDE * 2) + quad * 16) = v;
        }
        __syncthreads();

#pragma unroll
        for (int ks2 = 0; ks2 < 2; ks2++) {
            const unsigned kb = ks2 << 5;   // 16 bf16 = 32 bytes
            unsigned a_hi[4][4], a_lo[4][4], bf[4][2];
#pragma unroll
            for (int i = 0; i < 4; i++)
                ldsm_x4(a_hi[i][0], a_hi[i][1], a_hi[i][2], a_hi[i][3],
                        aHi + i * (16 * SSTRIDE * 2) + kb);
#pragma unroll
            for (int i = 0; i < 4; i++)
                ldsm_x4(a_lo[i][0], a_lo[i][1], a_lo[i][2], a_lo[i][3],
                        aLo + i * (16 * SSTRIDE * 2) + kb);

            // B-hi (4 n-tiles via two x4 loads)
            ldsm_x4(bf[0][0], bf[0][1], bf[1][0], bf[1][1], bHi + kb);
            ldsm_x4(bf[2][0], bf[2][1], bf[3][0], bf[3][1],
                    bHi + 16 * SSTRIDE * 2 + kb);
#pragma unroll
            for (int i = 0; i < 4; i++)
#pragma unroll
                for (int j = 0; j < 4; j++)
                    mma16816(acc[i][j], a_hi[i], bf[j]);
#pragma unroll
            for (int i = 0; i < 4; i++)
#pragma unroll
                for (int j = 0; j < 4; j++)
                    mma16816(acc[i][j], a_lo[i], bf[j]);

            // B-lo
            ldsm_x4(bf[0][0], bf[0][1], bf[1][0], bf[1][1], bLo + kb);
            ldsm_x4(bf[2][0], bf[2][1], bf[3][0], bf[3][1],
                    bLo + 16 * SSTRIDE * 2 + kb);
#pragma unroll
            for (int i = 0; i < 4; i++)
#pragma unroll
                for (int j = 0; j < 4; j++)
                    mma16816(acc[i][j], a_hi[i], bf[j]);
        }
    }

    // epilogue: thread (g,c): rows g,g+8 of each m16 tile; cols 2c,2c+1 of n8 tile
    const int g = lane >> 2;
    const int c = lane & 3;
#pragma unroll
    for (int i = 0; i < 4; i++) {
#pragma unroll
        for (int j = 0; j < 4; j++) {
            const int rm = m0 + warp_m + i * 16 + g;
            const int cn = n0 + warp_n + j * 8 + 2 * c;
            const float2 bv = *(const float2*)(bias + cn);
            float2 d0 = make_float2(acc[i][j][0] + bv.x, acc[i][j][1] + bv.y);
            float2 d1 = make_float2(acc[i][j][2] + bv.x, acc[i][j][3] + bv.y);
            if (MODE == 0) {
                const int which = cn >> 10;          // 0=Q,1=K,2=V
                const int head  = (cn & 1023) >> 6;
                const int hcol  = cn & 63;
                float* dstp = (which == 0) ? g_Q : (which == 1) ? g_K : g_V;
                const int b0r = rm >> 11, s0 = rm & 2047;
                const int b1r = (rm + 8) >> 11, s1 = (rm + 8) & 2047;
                *(float2*)(dstp + (((size_t)(b0r * NH + head)) * SEQ + s0) * DH + hcol) = d0;
                *(float2*)(dstp + (((size_t)(b1r * NH + head)) * SEQ + s1) * DH + hcol) = d1;
            } else {
                *(float2*)(Cout + (size_t)rm * DM + cn) = d0;
                *(float2*)(Cout + (size_t)(rm + 8) * DM + cn) = d1;
            }
        }
    }
}

// ---------------------------------------------------------------------------
// Causal flash attention, fp32 (unchanged from round 1).
// ---------------------------------------------------------------------------
#define FLASH_SMEM (4 * 64 * 68 * 4)

__global__ void __launch_bounds__(256) flash_kernel()
{
    extern __shared__ float smem[];
    float (*Qs)[68] = (float(*)[68])(smem);
    float (*Ks)[68] = (float(*)[68])(smem + 64 * 68);
    float (*Vs)[68] = (float(*)[68])(smem + 2 * 64 * 68);
    float (*Ps)[68] = (float(*)[68])(smem + 3 * 64 * 68);

    const int t  = threadIdx.x;
    const int tx = t & 15, ty = t >> 4;
    const int qt = blockIdx.x;
    const int h  = blockIdx.y;
    const int b  = blockIdx.z;
    const int q0 = qt << 6;

    const size_t base = ((size_t)(b * NH + h)) * SEQ * DH;
    const float* Qp = g_Q + base;
    const float* Kp = g_K + base;
    const float* Vp = g_V + base;

    const int lm = t >> 2;
    const int ld = (t & 3) << 2;

#pragma unroll
    for (int c = 0; c < 4; c++) {
        const int d = c * 16 + ld;
        float4 v = *(const float4*)(Qp + (size_t)(q0 + lm) * DH + d);
        Qs[d + 0][lm] = v.x; Qs[d + 1][lm] = v.y;
        Qs[d + 2][lm] = v.z; Qs[d + 3][lm] = v.w;
    }

    float o[4][4] = {};
    float mrow[4] = {-1e30f, -1e30f, -1e30f, -1e30f};
    float lrow[4] = {};

    for (int kt = 0; kt <= qt; kt++) {
        const int k0 = kt << 6;
        __syncthreads();
#pragma unroll
        for (int c = 0; c < 4; c++) {
            const int d = c * 16 + ld;
            float4 v = *(const float4*)(Kp + (size_t)(k0 + lm) * DH + d);
            Ks[d + 0][lm] = v.x; Ks[d + 1][lm] = v.y;
            Ks[d + 2][lm] = v.z; Ks[d + 3][lm] = v.w;
            float4 w = *(const float4*)(Vp + (size_t)(k0 + lm) * DH + d);
            *(float4*)(&Vs[lm][d]) = w;
        }
        __syncthreads();

        float s[4][4] = {};
#pragma unroll 8
        for (int d = 0; d < 64; d++) {
            float4 a  = *(const float4*)(&Qs[d][ty << 2]);
            float4 bq = *(const float4*)(&Ks[d][tx << 2]);
            float av[4] = {a.x, a.y, a.z, a.w};
            float bv[4] = {bq.x, bq.y, bq.z, bq.w};
#pragma unroll
            for (int i = 0; i < 4; i++)
#pragma unroll
                for (int j = 0; j < 4; j++)
                    s[i][j] += av[i] * bv[j];
        }

#pragma unroll
        for (int i = 0; i < 4; i++) {
            const int qi = q0 + (ty << 2) + i;
#pragma unroll
            for (int j = 0; j < 4; j++) {
                const int kj = k0 + (tx << 2) + j;
                s[i][j] = (kj <= qi) ? s[i][j] * 0.125f : -1e30f;
            }
        }

#pragma unroll
        for (int i = 0; i < 4; i++) {
            float rmax = fmaxf(fmaxf(s[i][0], s[i][1]), fmaxf(s[i][2], s[i][3]));
#pragma unroll
            for (int off = 8; off; off >>= 1)
                rmax = fmaxf(rmax, __shfl_xor_sync(0xffffffffu, rmax, off));
            const float mnew  = fmaxf(mrow[i], rmax);
            const float alpha = __expf(mrow[i] - mnew);
            const float p0 = __expf(s[i][0] - mnew);
            const float p1 = __expf(s[i][1] - mnew);
            const float p2 = __expf(s[i][2] - mnew);
            const float p3 = __expf(s[i][3] - mnew);
            float rsum = (p0 + p1) + (p2 + p3);
#pragma unroll
            for (int off = 8; off; off >>= 1)
                rsum += __shfl_xor_sync(0xffffffffu, rsum, off);
            lrow[i] = lrow[i] * alpha + rsum;
            mrow[i] = mnew;
            o[i][0] *= alpha; o[i][1] *= alpha; o[i][2] *= alpha; o[i][3] *= alpha;
            *(float4*)(&Ps[(ty << 2) + i][tx << 2]) = make_float4(p0, p1, p2, p3);
        }
        __syncthreads();

#pragma unroll 4
        for (int kk = 0; kk < 64; kk += 4) {
            float4 a0 = *(const float4*)(&Ps[(ty << 2) + 0][kk]);
            float4 a1 = *(const float4*)(&Ps[(ty << 2) + 1][kk]);
            float4 a2 = *(const float4*)(&Ps[(ty << 2) + 2][kk]);
            float4 a3 = *(const float4*)(&Ps[(ty << 2) + 3][kk]);
            float A0[4] = {a0.x, a0.y, a0.z, a0.w};
            float A1[4] = {a1.x, a1.y, a1.z, a1.w};
            float A2[4] = {a2.x, a2.y, a2.z, a2.w};
            float A3[4] = {a3.x, a3.y, a3.z, a3.w};
#pragma unroll
            for (int r = 0; r < 4; r++) {
                float4 bv = *(const float4*)(&Vs[kk + r][tx << 2]);
                float bb[4] = {bv.x, bv.y, bv.z, bv.w};
#pragma unroll
                for (int j = 0; j < 4; j++) {
                    o[0][j] += A0[r] * bb[j];
                    o[1][j] += A1[r] * bb[j];
                    o[2][j] += A2[r] * bb[j];
                    o[3][j] += A3[r] * bb[j];
                }
            }
        }
    }

#pragma unroll
    for (int i = 0; i < 4; i++) {
        const float inv = 1.0f / lrow[i];
        const int tok = b * SEQ + q0 + (ty << 2) + i;
        float4 ov = make_float4(o[i][0] * inv, o[i][1] * inv,
                                o[i][2] * inv, o[i][3] * inv);
        *(float4*)(&g_att[(size_t)tok * DM + h * DH + (tx << 2)]) = ov;
    }
}

// ---------------------------------------------------------------------------
extern "C" void kernel_launch(void* const* d_in, const int* in_sizes, int n_in,
                              void* d_out, int out_size)
{
    (void)in_sizes; (void)n_in; (void)out_size;
    const float* x    = (const float*)d_in[0];
    const float* Wqkv = (const float*)d_in[1];
    const float* bqkv = (const float*)d_in[2];
    const float* Wo   = (const float*)d_in[3];
    const float* bo   = (const float*)d_in[4];
    float* out = (float*)d_out;

    cudaFuncSetAttribute(flash_kernel,
                         cudaFuncAttributeMaxDynamicSharedMemorySize, FLASH_SMEM);

    // fp32 -> bf16 hi/lo splits
    split_kernel<<<(TOKENS * DM / 4 + 255) / 256, 256>>>(x,    0, TOKENS * DM / 4);
    split_kernel<<<(3 * DM * DM / 4 + 255) / 256, 256>>>(Wqkv, 1, 3 * DM * DM / 4);
    split_kernel<<<(DM * DM / 4 + 255) / 256, 256>>>(Wo,       2, DM * DM / 4);

    // QKV projection (tensor cores) -> scatter to g_Q/g_K/g_V
    tc_gemm_kernel<0><<<dim3(3 * DM / 128, TOKENS / 128), 256>>>(bqkv, nullptr);

    // Causal flash attention (fp32) -> g_att [B,S,D]
    flash_kernel<<<dim3(SEQ / 64, NH, BATCH), 256, FLASH_SMEM>>>();

    // att -> bf16 hi/lo, then output projection (tensor cores) -> d_out
    split_kernel<<<(TOKENS * DM / 4 + 255) / 256, 256>>>(nullptr, 3, TOKENS * DM / 4);
    tc_gemm_kernel<1><<<dim3(DM / 128, TOKENS / 128), 256>>>(bo, out);
}

// round 4
// speedup vs baseline: 2.6921x; 1.6295x over previous
#include <cuda_runtime.h>
#include <cuda_bf16.h>
#include <math.h>

#define DM     1024
#define NH     16
#define DH     64
#define BATCH  4
#define SEQ    2048
#define TOKENS (BATCH * SEQ)

// ---------------------------------------------------------------------------
// Scratch (static device memory — no allocations allowed)
// ---------------------------------------------------------------------------
__device__ __align__(16) __nv_bfloat16 g_xhi[TOKENS * DM];
__device__ __align__(16) __nv_bfloat16 g_xlo[TOKENS * DM];
__device__ __align__(16) __nv_bfloat16 g_wqkv_hi[3 * DM * DM];
__device__ __align__(16) __nv_bfloat16 g_wqkv_lo[3 * DM * DM];
__device__ __align__(16) __nv_bfloat16 g_wo_hi[DM * DM];
__device__ __align__(16) __nv_bfloat16 g_wo_lo[DM * DM];
__device__ __align__(16) __nv_bfloat16 g_ahi[TOKENS * DM];
__device__ __align__(16) __nv_bfloat16 g_alo[TOKENS * DM];
// Q/K/V in [B,H,S,DH] layout, bf16 hi/lo
__device__ __align__(16) __nv_bfloat16 g_Qhi[TOKENS * DM];
__device__ __align__(16) __nv_bfloat16 g_Qlo[TOKENS * DM];
__device__ __align__(16) __nv_bfloat16 g_Khi[TOKENS * DM];
__device__ __align__(16) __nv_bfloat16 g_Klo[TOKENS * DM];
__device__ __align__(16) __nv_bfloat16 g_Vhi[TOKENS * DM];
__device__ __align__(16) __nv_bfloat16 g_Vlo[TOKENS * DM];

// ---------------------------------------------------------------------------
// helpers
// ---------------------------------------------------------------------------
__device__ __forceinline__ unsigned smem_to_u32(const void* p) {
    unsigned a;
    asm("{ .reg .u64 t; cvta.to.shared.u64 t, %1; cvt.u32.u64 %0, t; }"
        : "=r"(a) : "l"(p));
    return a;
}

__device__ __forceinline__ void ldsm_x4(unsigned& r0, unsigned& r1,
                                        unsigned& r2, unsigned& r3,
                                        unsigned addr) {
    asm volatile("ldmatrix.sync.aligned.m8n8.x4.shared.b16 {%0,%1,%2,%3}, [%4];"
                 : "=r"(r0), "=r"(r1), "=r"(r2), "=r"(r3) : "r"(addr));
}

__device__ __forceinline__ void ldsm_x4_t(unsigned& r0, unsigned& r1,
                                          unsigned& r2, unsigned& r3,
                                          unsigned addr) {
    asm volatile("ldmatrix.sync.aligned.m8n8.x4.trans.shared.b16 {%0,%1,%2,%3}, [%4];"
                 : "=r"(r0), "=r"(r1), "=r"(r2), "=r"(r3) : "r"(addr));
}

__device__ __forceinline__ void mma16816(float* d, const unsigned* a,
                                         const unsigned* b) {
    asm volatile(
        "mma.sync.aligned.m16n8k16.row.col.f32.bf16.bf16.f32 "
        "{%0,%1,%2,%3}, {%4,%5,%6,%7}, {%8,%9}, {%0,%1,%2,%3};"
        : "+f"(d[0]), "+f"(d[1]), "+f"(d[2]), "+f"(d[3])
        : "r"(a[0]), "r"(a[1]), "r"(a[2]), "r"(a[3]), "r"(b[0]), "r"(b[1]));
}

__device__ __forceinline__ unsigned pack_bf2(__nv_bfloat16 a, __nv_bfloat16 b) {
    __nv_bfloat162 t = __halves2bfloat162(a, b);
    return *(unsigned*)&t;
}

// split two fp32 into bf16 hi/lo pairs and store as u32 each
__device__ __forceinline__ void split_store(__nv_bfloat16* hp, __nv_bfloat16* lp,
                                            size_t idx, float a, float b) {
    __nv_bfloat16 ha = __float2bfloat16_rn(a), hb = __float2bfloat16_rn(b);
    float la = a - __bfloat162float(ha), lb = b - __bfloat162float(hb);
    *(unsigned*)(hp + idx) = pack_bf2(ha, hb);
    *(unsigned*)(lp + idx) = pack_bf2(__float2bfloat16_rn(la), __float2bfloat16_rn(lb));
}

// ---------------------------------------------------------------------------
// fp32 -> bf16 hi/lo split for inputs. mode: 0=x, 1=W_qkv, 2=W_o
// ---------------------------------------------------------------------------
__global__ void __launch_bounds__(256) split_kernel(
    const float* __restrict__ src, int mode, int n4)
{
    int i = blockIdx.x * blockDim.x + threadIdx.x;
    if (i >= n4) return;
    float4 v = ((const float4*)src)[i];
    __nv_bfloat16 *hp, *lp;
    if (mode == 0)      { hp = g_xhi;     lp = g_xlo; }
    else if (mode == 1) { hp = g_wqkv_hi; lp = g_wqkv_lo; }
    else                { hp = g_wo_hi;   lp = g_wo_lo; }
    float f[4] = {v.x, v.y, v.z, v.w};
    __nv_bfloat16 h[4], l[4];
#pragma unroll
    for (int j = 0; j < 4; j++) {
        h[j] = __float2bfloat16(f[j]);
        l[j] = __float2bfloat16(f[j] - __bfloat162float(h[j]));
    }
    ((unsigned*)hp)[2 * i]     = pack_bf2(h[0], h[1]);
    ((unsigned*)hp)[2 * i + 1] = pack_bf2(h[2], h[3]);
    ((unsigned*)lp)[2 * i]     = pack_bf2(l[0], l[1]);
    ((unsigned*)lp)[2 * i + 1] = pack_bf2(l[2], l[3]);
}

// ---------------------------------------------------------------------------
// Tensor-core GEMM (mma.sync bf16, 3-term split), NT:
//   C[M,N] = A[M,K] @ B[N,K]^T + bias[N],  K = 1024
// CTA 128x128, 8 warps 64x32 each, BK=32.
// MODE 0: -> Q/K/V bf16 hi/lo (Q scaled by 0.125), [B,H,S,DH]
// MODE 1: -> fp32 row-major Cout
// ---------------------------------------------------------------------------
#define SSTRIDE 40

template <int MODE>
__global__ void __launch_bounds__(256, 2) tc_gemm_kernel(
    const float* __restrict__ bias, float* __restrict__ Cout)
{
    __shared__ __align__(16) __nv_bfloat16 sA[2][128][SSTRIDE];
    __shared__ __align__(16) __nv_bfloat16 sB[2][128][SSTRIDE];

    const int tid  = threadIdx.x;
    const int lane = tid & 31;
    const int wid  = tid >> 5;
    const int n0 = blockIdx.x << 7;
    const int m0 = blockIdx.y << 7;
    const int warp_m = (wid & 1) << 6;
    const int warp_n = (wid >> 1) << 5;

    const __nv_bfloat16* Ahi = (MODE == 0) ? g_xhi : g_ahi;
    const __nv_bfloat16* Alo = (MODE == 0) ? g_xlo : g_alo;
    const __nv_bfloat16* Bhi = (MODE == 0) ? g_wqkv_hi : g_wo_hi;
    const __nv_bfloat16* Blo = (MODE == 0) ? g_wqkv_lo : g_wo_lo;

    const int tl   = tid >> 6;
    const int t6   = tid & 63;
    const int quad = t6 & 3;
    const int rb   = t6 >> 2;
    const __nv_bfloat16* gsrc = (tl == 0) ? Ahi : (tl == 1) ? Alo
                              : (tl == 2) ? Bhi : Blo;
    const int rowoff = (tl < 2) ? m0 : n0;
    __nv_bfloat16* sdst = (tl == 0) ? &sA[0][0][0] : (tl == 1) ? &sA[1][0][0]
                        : (tl == 2) ? &sB[0][0][0] : &sB[1][0][0];
    const __nv_bfloat16* gp = gsrc + (size_t)(rowoff + rb) * DM + quad * 8;

    const unsigned sA_u = smem_to_u32(&sA[0][0][0]);
    const unsigned sB_u = smem_to_u32(&sB[0][0][0]);
    const unsigned aHi = sA_u + (warp_m + (lane & 15)) * (SSTRIDE * 2)
                              + ((lane >> 4) << 4);
    const unsigned aLo = aHi + 128 * SSTRIDE * 2;
    const unsigned bRow = warp_n + ((lane >> 4) << 3) + (lane & 7);
    const unsigned bHi = sB_u + bRow * (SSTRIDE * 2) + (((lane >> 3) & 1) << 4);
    const unsigned bLo = bHi + 128 * SSTRIDE * 2;

    float acc[4][4][4] = {};

    for (int kc = 0; kc < DM; kc += 32) {
        __syncthreads();
#pragma unroll
        for (int p = 0; p < 8; p++) {
            const int row = rb + p * 16;
            uint4 v = *(const uint4*)(gp + (size_t)p * 16 * DM + kc);
            *(uint4*)((char*)sdst + row * (SSTRIDE * 2) + quad * 16) = v;
        }
        __syncthreads();

#pragma unroll
        for (int ks2 = 0; ks2 < 2; ks2++) {
            const unsigned kb = ks2 << 5;
            unsigned a_hi[4][4], a_lo[4][4], bf[4][2];
#pragma unroll
            for (int i = 0; i < 4; i++)
                ldsm_x4(a_hi[i][0], a_hi[i][1], a_hi[i][2], a_hi[i][3],
                        aHi + i * (16 * SSTRIDE * 2) + kb);
#pragma unroll
            for (int i = 0; i < 4; i++)
                ldsm_x4(a_lo[i][0], a_lo[i][1], a_lo[i][2], a_lo[i][3],
                        aLo + i * (16 * SSTRIDE * 2) + kb);

            ldsm_x4(bf[0][0], bf[0][1], bf[1][0], bf[1][1], bHi + kb);
            ldsm_x4(bf[2][0], bf[2][1], bf[3][0], bf[3][1],
                    bHi + 16 * SSTRIDE * 2 + kb);
#pragma unroll
            for (int i = 0; i < 4; i++)
#pragma unroll
                for (int j = 0; j < 4; j++)
                    mma16816(acc[i][j], a_hi[i], bf[j]);
#pragma unroll
            for (int i = 0; i < 4; i++)
#pragma unroll
                for (int j = 0; j < 4; j++)
                    mma16816(acc[i][j], a_lo[i], bf[j]);

            ldsm_x4(bf[0][0], bf[0][1], bf[1][0], bf[1][1], bLo + kb);
            ldsm_x4(bf[2][0], bf[2][1], bf[3][0], bf[3][1],
                    bLo + 16 * SSTRIDE * 2 + kb);
#pragma unroll
            for (int i = 0; i < 4; i++)
#pragma unroll
                for (int j = 0; j < 4; j++)
                    mma16816(acc[i][j], a_hi[i], bf[j]);
        }
    }

    const int g = lane >> 2;
    const int c = lane & 3;
#pragma unroll
    for (int i = 0; i < 4; i++) {
#pragma unroll
        for (int j = 0; j < 4; j++) {
            const int rm = m0 + warp_m + i * 16 + g;
            const int cn = n0 + warp_n + j * 8 + 2 * c;
            const float2 bv = *(const float2*)(bias + cn);
            float v00 = acc[i][j][0] + bv.x, v01 = acc[i][j][1] + bv.y;
            float v10 = acc[i][j][2] + bv.x, v11 = acc[i][j][3] + bv.y;
            if (MODE == 0) {
                const int which = cn >> 10;           // 0=Q,1=K,2=V
                const int head  = (cn & 1023) >> 6;
                const int hcol  = cn & 63;
                __nv_bfloat16 *hp, *lp;
                if (which == 0)      { hp = g_Qhi; lp = g_Qlo;
                                       v00 *= 0.125f; v01 *= 0.125f;
                                       v10 *= 0.125f; v11 *= 0.125f; }
                else if (which == 1) { hp = g_Khi; lp = g_Klo; }
                else                 { hp = g_Vhi; lp = g_Vlo; }
                const int b0r = rm >> 11, s0 = rm & 2047;
                const int b1r = (rm + 8) >> 11, s1 = (rm + 8) & 2047;
                split_store(hp, lp,
                    (((size_t)(b0r * NH + head)) * SEQ + s0) * DH + hcol, v00, v01);
                split_store(hp, lp,
                    (((size_t)(b1r * NH + head)) * SEQ + s1) * DH + hcol, v10, v11);
            } else {
                *(float2*)(Cout + (size_t)rm * DM + cn) = make_float2(v00, v01);
                *(float2*)(Cout + (size_t)(rm + 8) * DM + cn) = make_float2(v10, v11);
            }
        }
    }
}

// ---------------------------------------------------------------------------
// Tensor-core causal flash attention (3-term bf16 splits).
// CTA: 128 q-rows of one (b,h); 8 warps x 16 rows. K-tiles of 64.
// Writes attention output directly as bf16 hi/lo into g_ahi/g_alo [B,S,DM].
// ---------------------------------------------------------------------------
#define FROWB 144          // smem row pitch bytes (72 bf16)
#define FTILE (64 * FROWB) // 9216 bytes per 64x64 tile

__global__ void __launch_bounds__(256) flash_tc_kernel()
{
    __shared__ __align__(16) char sbuf[4 * FTILE];  // Khi|Klo|Vhi|Vlo (Q staged first)

    const int tid  = threadIdx.x;
    const int lane = tid & 31;
    const int wid  = tid >> 5;
    const int warp_m = wid << 4;
    const int qt = (SEQ / 128 - 1) - blockIdx.x;   // longest CTAs first
    const int h  = blockIdx.y;
    const int b  = blockIdx.z;
    const int q0 = qt << 7;
    const int bh = b * NH + h;
    const size_t base = (size_t)bh * SEQ * DH;
    const unsigned sb = smem_to_u32(sbuf);

    // ---- stage Q hi/lo (128x64) and pull into A-fragments ----
    {
        const __nv_bfloat16* qh = g_Qhi + base + (size_t)q0 * DH;
        const __nv_bfloat16* ql = g_Qlo + base + (size_t)q0 * DH;
#pragma unroll
        for (int r = 0; r < 4; r++) {
            const int cc = tid + (r << 8);
            const int row = cc >> 3, ch = cc & 7;
            *(uint4*)(sbuf + row * FROWB + ch * 16) =
                *(const uint4*)(qh + row * DH + ch * 8);
            *(uint4*)(sbuf + 2 * FTILE + row * FROWB + ch * 16) =
                *(const uint4*)(ql + row * DH + ch * 8);
        }
    }
    __syncthreads();
    unsigned qf_hi[4][4], qf_lo[4][4];
    {
        const unsigned qa = sb + (warp_m + (lane & 15)) * FROWB + ((lane >> 4) << 4);
#pragma unroll
        for (int t = 0; t < 4; t++) {
            ldsm_x4(qf_hi[t][0], qf_hi[t][1], qf_hi[t][2], qf_hi[t][3], qa + t * 32);
            ldsm_x4(qf_lo[t][0], qf_lo[t][1], qf_lo[t][2], qf_lo[t][3],
                    qa + 2 * FTILE + t * 32);
        }
    }
    __syncthreads();

    float o[8][4] = {};
    float m0 = -1e30f, m1 = -1e30f, l0 = 0.f, l1 = 0.f;
    const int g  = lane >> 2;
    const int c4 = lane & 3;
    const int row0 = q0 + warp_m + g;
    const int row1 = row0 + 8;

    const unsigned ka = sb + ((lane & 7) + ((lane >> 4) << 3)) * FROWB
                           + (((lane >> 3) & 1) << 4);
    const unsigned va = sb + 2 * FTILE
                           + ((lane & 7) + (((lane >> 3) & 1) << 3)) * FROWB
                           + ((lane >> 4) << 4);

    const int nkt = (q0 >> 6) + 2;
    for (int kt = 0; kt < nkt; kt++) {
        const int k0 = kt << 6;
        // ---- stage Khi,Klo,Vhi,Vlo 64x64 tiles ----
        {
            const __nv_bfloat16* p0 = g_Khi + base + (size_t)k0 * DH;
            const __nv_bfloat16* p1 = g_Klo + base + (size_t)k0 * DH;
            const __nv_bfloat16* p2 = g_Vhi + base + (size_t)k0 * DH;
            const __nv_bfloat16* p3 = g_Vlo + base + (size_t)k0 * DH;
#pragma unroll
            for (int r = 0; r < 2; r++) {
                const int cc = tid + (r << 8);
                const int row = cc >> 3, ch = cc & 7;
                const int so = row * FROWB + ch * 16;
                const int go = row * DH + ch * 8;
                *(uint4*)(sbuf + 0 * FTILE + so) = *(const uint4*)(p0 + go);
                *(uint4*)(sbuf + 1 * FTILE + so) = *(const uint4*)(p1 + go);
                *(uint4*)(sbuf + 2 * FTILE + so) = *(const uint4*)(p2 + go);
                *(uint4*)(sbuf + 3 * FTILE + so) = *(const uint4*)(p3 + go);
            }
        }
        __syncthreads();

        if (k0 <= q0 + warp_m + 15) {   // warp has live rows in this tile
            // ---- S = Q K^T (3-term) ----
            float s[8][4];
#pragma unroll
            for (int j = 0; j < 8; j++)
#pragma unroll
                for (int x = 0; x < 4; x++) s[j][x] = 0.f;

#pragma unroll
            for (int t = 0; t < 4; t++) {
                unsigned kf[8][2];
#pragma unroll
                for (int jp = 0; jp < 4; jp++)
                    ldsm_x4(kf[2 * jp][0], kf[2 * jp][1],
                            kf[2 * jp + 1][0], kf[2 * jp + 1][1],
                            ka + jp * (16 * FROWB) + t * 32);
#pragma unroll
                for (int j = 0; j < 8; j++) mma16816(s[j], qf_hi[t], kf[j]);
#pragma unroll
                for (int j = 0; j < 8; j++) mma16816(s[j], qf_lo[t], kf[j]);
#pragma unroll
                for (int jp = 0; jp < 4; jp++)
                    ldsm_x4(kf[2 * jp][0], kf[2 * jp][1],
                            kf[2 * jp + 1][0], kf[2 * jp + 1][1],
                            ka + FTILE + jp * (16 * FROWB) + t * 32);
#pragma unroll
                for (int j = 0; j < 8; j++) mma16816(s[j], qf_hi[t], kf[j]);
            }

            // ---- causal mask ----
            if (k0 + 63 > q0 + warp_m) {
#pragma unroll
                for (int j = 0; j < 8; j++) {
                    const int col = k0 + 8 * j + 2 * c4;
                    if (col     > row0) s[j][0] = -1e30f;
                    if (col + 1 > row0) s[j][1] = -1e30f;
                    if (col     > row1) s[j][2] = -1e30f;
                    if (col + 1 > row1) s[j][3] = -1e30f;
                }
            }

            // ---- online softmax (2 rows/thread, quad shfl reduce) ----
            float rx0 = -1e30f, rx1 = -1e30f;
#pragma unroll
            for (int j = 0; j < 8; j++) {
                rx0 = fmaxf(rx0, fmaxf(s[j][0], s[j][1]));
                rx1 = fmaxf(rx1, fmaxf(s[j][2], s[j][3]));
            }
            rx0 = fmaxf(rx0, __shfl_xor_sync(0xffffffffu, rx0, 1));
            rx0 = fmaxf(rx0, __shfl_xor_sync(0xffffffffu, rx0, 2));
            rx1 = fmaxf(rx1, __shfl_xor_sync(0xffffffffu, rx1, 1));
            rx1 = fmaxf(rx1, __shfl_xor_sync(0xffffffffu, rx1, 2));
            const float mn0 = fmaxf(m0, rx0), mn1 = fmaxf(m1, rx1);
            const float a0 = __expf(m0 - mn0), a1 = __expf(m1 - mn1);
            float sum0 = 0.f, sum1 = 0.f;
#pragma unroll
            for (int j = 0; j < 8; j++) {
                s[j][0] = __expf(s[j][0] - mn0);
                s[j][1] = __expf(s[j][1] - mn0);
                s[j][2] = __expf(s[j][2] - mn1);
                s[j][3] = __expf(s[j][3] - mn1);
                sum0 += s[j][0] + s[j][1];
                sum1 += s[j][2] + s[j][3];
            }
            sum0 += __shfl_xor_sync(0xffffffffu, sum0, 1);
            sum0 += __shfl_xor_sync(0xffffffffu, sum0, 2);
            sum1 += __shfl_xor_sync(0xffffffffu, sum1, 1);
            sum1 += __shfl_xor_sync(0xffffffffu, sum1, 2);
            l0 = l0 * a0 + sum0;  l1 = l1 * a1 + sum1;
            m0 = mn0;  m1 = mn1;
#pragma unroll
            for (int j = 0; j < 8; j++) {
                o[j][0] *= a0; o[j][1] *= a0; o[j][2] *= a1; o[j][3] *= a1;
            }

            // ---- O += P V (3-term, P register-resident) ----
#pragma unroll
            for (int t = 0; t < 4; t++) {
                unsigned ahi[4], alo[4];
                {
                    const float p0 = s[2 * t][0],     p1 = s[2 * t][1];
                    const float p2 = s[2 * t][2],     p3 = s[2 * t][3];
                    const float r0 = s[2 * t + 1][0], r1 = s[2 * t + 1][1];
                    const float r2 = s[2 * t + 1][2], r3 = s[2 * t + 1][3];
                    __nv_bfloat16 h0 = __float2bfloat16_rn(p0), h1 = __float2bfloat16_rn(p1);
                    __nv_bfloat16 h2 = __float2bfloat16_rn(p2), h3 = __float2bfloat16_rn(p3);
                    __nv_bfloat16 e0 = __float2bfloat16_rn(r0), e1 = __float2bfloat16_rn(r1);
                    __nv_bfloat16 e2 = __float2bfloat16_rn(r2), e3 = __float2bfloat16_rn(r3);
                    ahi[0] = pack_bf2(h0, h1); ahi[1] = pack_bf2(h2, h3);
                    ahi[2] = pack_bf2(e0, e1); ahi[3] = pack_bf2(e2, e3);
                    alo[0] = pack_bf2(__float2bfloat16_rn(p0 - __bfloat162float(h0)),
                                      __float2bfloat16_rn(p1 - __bfloat162float(h1)));
                    alo[1] = pack_bf2(__float2bfloat16_rn(p2 - __bfloat162float(h2)),
                                      __float2bfloat16_rn(p3 - __bfloat162float(h3)));
                    alo[2] = pack_bf2(__float2bfloat16_rn(r0 - __bfloat162float(e0)),
                                      __float2bfloat16_rn(r1 - __bfloat162float(e1)));
                    alo[3] = pack_bf2(__float2bfloat16_rn(r2 - __bfloat162float(e2)),
                                      __float2bfloat16_rn(r3 - __bfloat162float(e3)));
                }
#pragma unroll
                for (int j2 = 0; j2 < 4; j2++) {
                    unsigned v0, v1, v2, v3;
                    ldsm_x4_t(v0, v1, v2, v3, va + t * (16 * FROWB) + j2 * 32);
                    unsigned bA[2] = {v0, v1}, bB[2] = {v2, v3};
                    mma16816(o[2 * j2],     ahi, bA);
                    mma16816(o[2 * j2 + 1], ahi, bB);
                    mma16816(o[2 * j2],     alo, bA);
                    mma16816(o[2 * j2 + 1], alo, bB);
                }
#pragma unroll
                for (int j2 = 0; j2 < 4; j2++) {
                    unsigned v0, v1, v2, v3;
                    ldsm_x4_t(v0, v1, v2, v3,
                              va + FTILE + t * (16 * FROWB) + j2 * 32);
                    unsigned bA[2] = {v0, v1}, bB[2] = {v2, v3};
                    mma16816(o[2 * j2],     ahi, bA);
                    mma16816(o[2 * j2 + 1], ahi, bB);
                }
            }
        }
        __syncthreads();
    }

    // ---- epilogue: normalize, split-store to g_ahi/g_alo [B,S,DM] ----
    const float i0 = 1.f / l0, i1 = 1.f / l1;
    const int tok0 = b * SEQ + q0 + warp_m + g;
    const int tok1 = tok0 + 8;
    const int colb = h * DH + 2 * c4;
#pragma unroll
    for (int j = 0; j < 8; j++) {
        split_store(g_ahi, g_alo, (size_t)tok0 * DM + colb + 8 * j,
                    o[j][0] * i0, o[j][1] * i0);
        split_store(g_ahi, g_alo, (size_t)tok1 * DM + colb + 8 * j,
                    o[j][2] * i1, o[j][3] * i1);
    }
}

// ---------------------------------------------------------------------------
extern "C" void kernel_launch(void* const* d_in, const int* in_sizes, int n_in,
                              void* d_out, int out_size)
{
    (void)in_sizes; (void)n_in; (void)out_size;
    const float* x    = (const float*)d_in[0];
    const float* Wqkv = (const float*)d_in[1];
    const float* bqkv = (const float*)d_in[2];
    const float* Wo   = (const float*)d_in[3];
    const float* bo   = (const float*)d_in[4];
    float* out = (float*)d_out;

    // fp32 -> bf16 hi/lo splits
    split_kernel<<<(TOKENS * DM / 4 + 255) / 256, 256>>>(x,    0, TOKENS * DM / 4);
    split_kernel<<<(3 * DM * DM / 4 + 255) / 256, 256>>>(Wqkv, 1, 3 * DM * DM / 4);
    split_kernel<<<(DM * DM / 4 + 255) / 256, 256>>>(Wo,       2, DM * DM / 4);

    // QKV projection -> Q/K/V bf16 hi/lo (Q pre-scaled)
    tc_gemm_kernel<0><<<dim3(3 * DM / 128, TOKENS / 128), 256>>>(bqkv, nullptr);

    // causal flash attention (tensor cores) -> g_ahi/g_alo
    flash_tc_kernel<<<dim3(SEQ / 128, NH, BATCH), 256>>>();

    // output projection -> d_out
    tc_gemm_kernel<1><<<dim3(DM / 128, TOKENS / 128), 256>>>(bo, out);
}

// round 5
// speedup vs baseline: 3.0075x; 1.1171x over previous
#include <cuda_runtime.h>
#include <cuda_bf16.h>
#include <math.h>

#define DM     1024
#define NH     16
#define DH     64
#define BATCH  4
#define SEQ    2048
#define TOKENS (BATCH * SEQ)

// ---------------------------------------------------------------------------
// Scratch (static device memory — no allocations allowed)
// ---------------------------------------------------------------------------
__device__ __align__(16) __nv_bfloat16 g_xhi[TOKENS * DM];
__device__ __align__(16) __nv_bfloat16 g_xlo[TOKENS * DM];
__device__ __align__(16) __nv_bfloat16 g_wqkv_hi[3 * DM * DM];
__device__ __align__(16) __nv_bfloat16 g_wqkv_lo[3 * DM * DM];
__device__ __align__(16) __nv_bfloat16 g_wo_hi[DM * DM];
__device__ __align__(16) __nv_bfloat16 g_wo_lo[DM * DM];
__device__ __align__(16) __nv_bfloat16 g_ahi[TOKENS * DM];
__device__ __align__(16) __nv_bfloat16 g_alo[TOKENS * DM];
__device__ __align__(16) __nv_bfloat16 g_Qhi[TOKENS * DM];
__device__ __align__(16) __nv_bfloat16 g_Qlo[TOKENS * DM];
__device__ __align__(16) __nv_bfloat16 g_Khi[TOKENS * DM];
__device__ __align__(16) __nv_bfloat16 g_Klo[TOKENS * DM];
__device__ __align__(16) __nv_bfloat16 g_Vhi[TOKENS * DM];
__device__ __align__(16) __nv_bfloat16 g_Vlo[TOKENS * DM];

// ---------------------------------------------------------------------------
// helpers
// ---------------------------------------------------------------------------
__device__ __forceinline__ unsigned smem_to_u32(const void* p) {
    unsigned a;
    asm("{ .reg .u64 t; cvta.to.shared.u64 t, %1; cvt.u32.u64 %0, t; }"
        : "=r"(a) : "l"(p));
    return a;
}

#define CP_ASYNC16(saddr, gptr) \
    asm volatile("cp.async.cg.shared.global [%0], [%1], 16;" \
                 :: "r"((unsigned)(saddr)), "l"(gptr))
#define CP_COMMIT() asm volatile("cp.async.commit_group;" ::: "memory")
#define CP_WAIT(n)  asm volatile("cp.async.wait_group %0;" :: "n"(n) : "memory")

__device__ __forceinline__ void ldsm_x4(unsigned& r0, unsigned& r1,
                                        unsigned& r2, unsigned& r3,
                                        unsigned addr) {
    asm volatile("ldmatrix.sync.aligned.m8n8.x4.shared.b16 {%0,%1,%2,%3}, [%4];"
                 : "=r"(r0), "=r"(r1), "=r"(r2), "=r"(r3) : "r"(addr));
}

__device__ __forceinline__ void ldsm_x4_t(unsigned& r0, unsigned& r1,
                                          unsigned& r2, unsigned& r3,
                                          unsigned addr) {
    asm volatile("ldmatrix.sync.aligned.m8n8.x4.trans.shared.b16 {%0,%1,%2,%3}, [%4];"
                 : "=r"(r0), "=r"(r1), "=r"(r2), "=r"(r3) : "r"(addr));
}

__device__ __forceinline__ void mma16816(float* d, const unsigned* a,
                                         const unsigned* b) {
    asm volatile(
        "mma.sync.aligned.m16n8k16.row.col.f32.bf16.bf16.f32 "
        "{%0,%1,%2,%3}, {%4,%5,%6,%7}, {%8,%9}, {%0,%1,%2,%3};"
        : "+f"(d[0]), "+f"(d[1]), "+f"(d[2]), "+f"(d[3])
        : "r"(a[0]), "r"(a[1]), "r"(a[2]), "r"(a[3]), "r"(b[0]), "r"(b[1]));
}

__device__ __forceinline__ unsigned pack_bf2(__nv_bfloat16 a, __nv_bfloat16 b) {
    __nv_bfloat162 t = __halves2bfloat162(a, b);
    return *(unsigned*)&t;
}

__device__ __forceinline__ void split_store(__nv_bfloat16* hp, __nv_bfloat16* lp,
                                            size_t idx, float a, float b) {
    __nv_bfloat16 ha = __float2bfloat16_rn(a), hb = __float2bfloat16_rn(b);
    float la = a - __bfloat162float(ha), lb = b - __bfloat162float(hb);
    *(unsigned*)(hp + idx) = pack_bf2(ha, hb);
    *(unsigned*)(lp + idx) = pack_bf2(__float2bfloat16_rn(la), __float2bfloat16_rn(lb));
}

// ---------------------------------------------------------------------------
// fp32 -> bf16 hi/lo split for inputs. mode: 0=x, 1=W_qkv, 2=W_o
// ---------------------------------------------------------------------------
__global__ void __launch_bounds__(256) split_kernel(
    const float* __restrict__ src, int mode, int n4)
{
    int i = blockIdx.x * blockDim.x + threadIdx.x;
    if (i >= n4) return;
    float4 v = ((const float4*)src)[i];
    __nv_bfloat16 *hp, *lp;
    if (mode == 0)      { hp = g_xhi;     lp = g_xlo; }
    else if (mode == 1) { hp = g_wqkv_hi; lp = g_wqkv_lo; }
    else                { hp = g_wo_hi;   lp = g_wo_lo; }
    float f[4] = {v.x, v.y, v.z, v.w};
    __nv_bfloat16 h[4], l[4];
#pragma unroll
    for (int j = 0; j < 4; j++) {
        h[j] = __float2bfloat16(f[j]);
        l[j] = __float2bfloat16(f[j] - __bfloat162float(h[j]));
    }
    ((unsigned*)hp)[2 * i]     = pack_bf2(h[0], h[1]);
    ((unsigned*)hp)[2 * i + 1] = pack_bf2(h[2], h[3]);
    ((unsigned*)lp)[2 * i]     = pack_bf2(l[0], l[1]);
    ((unsigned*)lp)[2 * i + 1] = pack_bf2(l[2], l[3]);
}

// ---------------------------------------------------------------------------
// Tensor-core GEMM, cp.async double-buffered. NT, K=1024, CTA 128x128,
// 8 warps 64x32, BK=32.
// MODE 0: -> Q/K/V bf16 hi/lo (Q scaled 0.125), [B,H,S,DH]
// MODE 1: -> fp32 row-major Cout
// ---------------------------------------------------------------------------
#define GTILE  10240                 // 128 rows x 80B pitch
#define GSTAGE (4 * GTILE)           // Ahi|Alo|Bhi|Blo
#define GEMM_SMEM (2 * GSTAGE)       // 81920 B

template <int MODE>
__global__ void __launch_bounds__(256, 2) tc_gemm_kernel(
    const float* __restrict__ bias, float* __restrict__ Cout)
{
    extern __shared__ __align__(16) char gsm[];

    const int tid  = threadIdx.x;
    const int lane = tid & 31;
    const int wid  = tid >> 5;
    const int n0 = blockIdx.x << 7;
    const int m0 = blockIdx.y << 7;
    const int warp_m = (wid & 1) << 6;
    const int warp_n = (wid >> 1) << 5;
    const unsigned sbase = smem_to_u32(gsm);

    const __nv_bfloat16* Ahi = (MODE == 0) ? g_xhi : g_ahi;
    const __nv_bfloat16* Alo = (MODE == 0) ? g_xlo : g_alo;
    const __nv_bfloat16* Bhi = (MODE == 0) ? g_wqkv_hi : g_wo_hi;
    const __nv_bfloat16* Blo = (MODE == 0) ? g_wqkv_lo : g_wo_lo;

    // staging assignment: 64 threads per tile, 16B per cp.async, 8 rows apart
    const int tl   = tid >> 6;
    const int t6   = tid & 63;
    const int quad = t6 & 3;
    const int rb   = t6 >> 2;
    const __nv_bfloat16* gsrc = (tl == 0) ? Ahi : (tl == 1) ? Alo
                              : (tl == 2) ? Bhi : Blo;
    const int rowoff = (tl < 2) ? m0 : n0;
    const __nv_bfloat16* gp = gsrc + (size_t)(rowoff + rb) * DM + quad * 8;
    const unsigned sdst = sbase + tl * GTILE + rb * 80 + quad * 16;

    // fragment lane addressing (stage offset added in loop)
    const unsigned aHi0 = sbase + (warp_m + (lane & 15)) * 80 + ((lane >> 4) << 4);
    const unsigned bRow = warp_n + ((lane >> 4) << 3) + (lane & 7);
    const unsigned bHi0 = sbase + 2 * GTILE + bRow * 80 + (((lane >> 3) & 1) << 4);

    float acc[4][4][4] = {};

    // prologue: prefetch chunk 0 into stage 0
    {
#pragma unroll
        for (int p = 0; p < 8; p++)
            CP_ASYNC16(sdst + p * (16 * 80), gp + (size_t)p * 16 * DM);
        CP_COMMIT();
    }

    for (int c = 0; c < 32; c++) {
        if (c + 1 < 32) {
            const unsigned so = sdst + ((c + 1) & 1) * GSTAGE;
            const __nv_bfloat16* g0 = gp + (c + 1) * 32;
#pragma unroll
            for (int p = 0; p < 8; p++)
                CP_ASYNC16(so + p * (16 * 80), g0 + (size_t)p * 16 * DM);
            CP_COMMIT();
            CP_WAIT(1);
        } else {
            CP_WAIT(0);
        }
        __syncthreads();

        const unsigned stof = (c & 1) * GSTAGE;
        const unsigned aHi = aHi0 + stof;
        const unsigned aLo = aHi + GTILE;
        const unsigned bHi = bHi0 + stof;
        const unsigned bLo = bHi + GTILE;

#pragma unroll
        for (int ks2 = 0; ks2 < 2; ks2++) {
            const unsigned kb = ks2 << 5;
            unsigned a_hi[4][4], a_lo[4][4], bf[4][2];
#pragma unroll
            for (int i = 0; i < 4; i++)
                ldsm_x4(a_hi[i][0], a_hi[i][1], a_hi[i][2], a_hi[i][3],
                        aHi + i * (16 * 80) + kb);
#pragma unroll
            for (int i = 0; i < 4; i++)
                ldsm_x4(a_lo[i][0], a_lo[i][1], a_lo[i][2], a_lo[i][3],
                        aLo + i * (16 * 80) + kb);

            ldsm_x4(bf[0][0], bf[0][1], bf[1][0], bf[1][1], bHi + kb);
            ldsm_x4(bf[2][0], bf[2][1], bf[3][0], bf[3][1],
                    bHi + 16 * 80 + kb);
#pragma unroll
            for (int i = 0; i < 4; i++)
#pragma unroll
                for (int j = 0; j < 4; j++)
                    mma16816(acc[i][j], a_hi[i], bf[j]);
#pragma unroll
            for (int i = 0; i < 4; i++)
#pragma unroll
                for (int j = 0; j < 4; j++)
                    mma16816(acc[i][j], a_lo[i], bf[j]);

            ldsm_x4(bf[0][0], bf[0][1], bf[1][0], bf[1][1], bLo + kb);
            ldsm_x4(bf[2][0], bf[2][1], bf[3][0], bf[3][1],
                    bLo + 16 * 80 + kb);
#pragma unroll
            for (int i = 0; i < 4; i++)
#pragma unroll
                for (int j = 0; j < 4; j++)
                    mma16816(acc[i][j], a_hi[i], bf[j]);
        }
        __syncthreads();
    }

    const int g = lane >> 2;
    const int c = lane & 3;
#pragma unroll
    for (int i = 0; i < 4; i++) {
#pragma unroll
        for (int j = 0; j < 4; j++) {
            const int rm = m0 + warp_m + i * 16 + g;
            const int cn = n0 + warp_n + j * 8 + 2 * c;
            const float2 bv = *(const float2*)(bias + cn);
            float v00 = acc[i][j][0] + bv.x, v01 = acc[i][j][1] + bv.y;
            float v10 = acc[i][j][2] + bv.x, v11 = acc[i][j][3] + bv.y;
            if (MODE == 0) {
                const int which = cn >> 10;
                const int head  = (cn & 1023) >> 6;
                const int hcol  = cn & 63;
                __nv_bfloat16 *hp, *lp;
                if (which == 0)      { hp = g_Qhi; lp = g_Qlo;
                                       v00 *= 0.125f; v01 *= 0.125f;
                                       v10 *= 0.125f; v11 *= 0.125f; }
                else if (which == 1) { hp = g_Khi; lp = g_Klo; }
                else                 { hp = g_Vhi; lp = g_Vlo; }
                const int b0r = rm >> 11, s0 = rm & 2047;
                const int b1r = (rm + 8) >> 11, s1 = (rm + 8) & 2047;
                split_store(hp, lp,
                    (((size_t)(b0r * NH + head)) * SEQ + s0) * DH + hcol, v00, v01);
                split_store(hp, lp,
                    (((size_t)(b1r * NH + head)) * SEQ + s1) * DH + hcol, v10, v11);
            } else {
                *(float2*)(Cout + (size_t)rm * DM + cn) = make_float2(v00, v01);
                *(float2*)(Cout + (size_t)(rm + 8) * DM + cn) = make_float2(v10, v11);
            }
        }
    }
}

// ---------------------------------------------------------------------------
// Tensor-core causal flash attention, cp.async double-buffered K/V tiles.
// CTA: 128 q-rows of one (b,h); 8 warps x 16 rows; K-tiles of 64.
// ---------------------------------------------------------------------------
#define FROWB 144
#define FTILE (64 * FROWB)          // 9216
#define FSTAGE (4 * FTILE)          // Khi|Klo|Vhi|Vlo = 36864
#define FLASH_SMEM (2 * FSTAGE)     // 73728

__global__ void __launch_bounds__(256) flash_tc_kernel()
{
    extern __shared__ __align__(16) char fsm[];

    const int tid  = threadIdx.x;
    const int lane = tid & 31;
    const int wid  = tid >> 5;
    const int warp_m = wid << 4;
    const int qt = (SEQ / 128 - 1) - blockIdx.x;
    const int h  = blockIdx.y;
    const int b  = blockIdx.z;
    const int q0 = qt << 7;
    const int bh = b * NH + h;
    const size_t base = (size_t)bh * SEQ * DH;
    const unsigned sb = smem_to_u32(fsm);

    // ---- stage Q hi/lo into stage-0 buffer, extract fragments ----
    {
        const __nv_bfloat16* qh = g_Qhi + base + (size_t)q0 * DH;
        const __nv_bfloat16* ql = g_Qlo + base + (size_t)q0 * DH;
#pragma unroll
        for (int r = 0; r < 4; r++) {
            const int cc = tid + (r << 8);
            const int row = cc >> 3, ch = cc & 7;
            *(uint4*)(fsm + row * FROWB + ch * 16) =
                *(const uint4*)(qh + row * DH + ch * 8);
            *(uint4*)(fsm + 2 * FTILE + row * FROWB + ch * 16) =
                *(const uint4*)(ql + row * DH + ch * 8);
        }
    }
    __syncthreads();
    unsigned qf_hi[4][4], qf_lo[4][4];
    {
        const unsigned qa = sb + (warp_m + (lane & 15)) * FROWB + ((lane >> 4) << 4);
#pragma unroll
        for (int t = 0; t < 4; t++) {
            ldsm_x4(qf_hi[t][0], qf_hi[t][1], qf_hi[t][2], qf_hi[t][3], qa + t * 32);
            ldsm_x4(qf_lo[t][0], qf_lo[t][1], qf_lo[t][2], qf_lo[t][3],
                    qa + 2 * FTILE + t * 32);
        }
    }
    __syncthreads();

    float o[8][4] = {};
    float m0 = -1e30f, m1 = -1e30f, l0 = 0.f, l1 = 0.f;
    const int g  = lane >> 2;
    const int c4 = lane & 3;
    const int row0 = q0 + warp_m + g;
    const int row1 = row0 + 8;

    const unsigned ka0 = sb + ((lane & 7) + ((lane >> 4) << 3)) * FROWB
                            + (((lane >> 3) & 1) << 4);
    const unsigned va0 = sb + 2 * FTILE
                            + ((lane & 7) + (((lane >> 3) & 1) << 3)) * FROWB
                            + ((lane >> 4) << 4);

    // staging thread map: 2 x (row = cc>>3, ch = cc&7), 4 tiles each
    const int srow = tid >> 3, sch = tid & 7;
    const unsigned sso = srow * FROWB + sch * 16;
    const unsigned sgo = srow * DH + sch * 8;

    const int nkt = (q0 >> 6) + 2;

    // prologue: prefetch tile 0 into stage 0
    {
        const __nv_bfloat16* p0 = g_Khi + base;
        const __nv_bfloat16* p1 = g_Klo + base;
        const __nv_bfloat16* p2 = g_Vhi + base;
        const __nv_bfloat16* p3 = g_Vlo + base;
#pragma unroll
        for (int r = 0; r < 2; r++) {
            const unsigned so = sso + r * (32 * FROWB);
            const unsigned go = sgo + r * (32 * DH);
            CP_ASYNC16(sb + 0 * FTILE + so, p0 + go);
            CP_ASYNC16(sb + 1 * FTILE + so, p1 + go);
            CP_ASYNC16(sb + 2 * FTILE + so, p2 + go);
            CP_ASYNC16(sb + 3 * FTILE + so, p3 + go);
        }
        CP_COMMIT();
    }

    for (int kt = 0; kt < nkt; kt++) {
        const int k0 = kt << 6;
        if (kt + 1 < nkt) {
            const size_t nb = base + (size_t)((kt + 1) << 6) * DH;
            const unsigned st = sb + ((kt + 1) & 1) * FSTAGE;
            const __nv_bfloat16* p0 = g_Khi + nb;
            const __nv_bfloat16* p1 = g_Klo + nb;
            const __nv_bfloat16* p2 = g_Vhi + nb;
            const __nv_bfloat16* p3 = g_Vlo + nb;
#pragma unroll
            for (int r = 0; r < 2; r++) {
                const unsigned so = sso + r * (32 * FROWB);
                const unsigned go = sgo + r * (32 * DH);
                CP_ASYNC16(st + 0 * FTILE + so, p0 + go);
                CP_ASYNC16(st + 1 * FTILE + so, p1 + go);
                CP_ASYNC16(st + 2 * FTILE + so, p2 + go);
                CP_ASYNC16(st + 3 * FTILE + so, p3 + go);
            }
            CP_COMMIT();
            CP_WAIT(1);
        } else {
            CP_WAIT(0);
        }
        __syncthreads();

        if (k0 <= q0 + warp_m + 15) {
            const unsigned stof = (kt & 1) * FSTAGE;
            const unsigned ka = ka0 + stof;
            const unsigned va = va0 + stof;

            float s[8][4];
#pragma unroll
            for (int j = 0; j < 8; j++)
#pragma unroll
                for (int x = 0; x < 4; x++) s[j][x] = 0.f;

#pragma unroll
            for (int t = 0; t < 4; t++) {
                unsigned kf[8][2];
#pragma unroll
                for (int jp = 0; jp < 4; jp++)
                    ldsm_x4(kf[2 * jp][0], kf[2 * jp][1],
                            kf[2 * jp + 1][0], kf[2 * jp + 1][1],
                            ka + jp * (16 * FROWB) + t * 32);
#pragma unroll
                for (int j = 0; j < 8; j++) mma16816(s[j], qf_hi[t], kf[j]);
#pragma unroll
                for (int j = 0; j < 8; j++) mma16816(s[j], qf_lo[t], kf[j]);
#pragma unroll
                for (int jp = 0; jp < 4; jp++)
                    ldsm_x4(kf[2 * jp][0], kf[2 * jp][1],
                            kf[2 * jp + 1][0], kf[2 * jp + 1][1],
                            ka + FTILE + jp * (16 * FROWB) + t * 32);
#pragma unroll
                for (int j = 0; j < 8; j++) mma16816(s[j], qf_hi[t], kf[j]);
            }

            if (k0 + 63 > q0 + warp_m) {
#pragma unroll
                for (int j = 0; j < 8; j++) {
                    const int col = k0 + 8 * j + 2 * c4;
                    if (col     > row0) s[j][0] = -1e30f;
                    if (col + 1 > row0) s[j][1] = -1e30f;
                    if (col     > row1) s[j][2] = -1e30f;
                    if (col + 1 > row1) s[j][3] = -1e30f;
                }
            }

            float rx0 = -1e30f, rx1 = -1e30f;
#pragma unroll
            for (int j = 0; j < 8; j++) {
                rx0 = fmaxf(rx0, fmaxf(s[j][0], s[j][1]));
                rx1 = fmaxf(rx1, fmaxf(s[j][2], s[j][3]));
            }
            rx0 = fmaxf(rx0, __shfl_xor_sync(0xffffffffu, rx0, 1));
            rx0 = fmaxf(rx0, __shfl_xor_sync(0xffffffffu, rx0, 2));
            rx1 = fmaxf(rx1, __shfl_xor_sync(0xffffffffu, rx1, 1));
            rx1 = fmaxf(rx1, __shfl_xor_sync(0xffffffffu, rx1, 2));
            const float mn0 = fmaxf(m0, rx0), mn1 = fmaxf(m1, rx1);
            const float a0 = __expf(m0 - mn0), a1 = __expf(m1 - mn1);
            float sum0 = 0.f, sum1 = 0.f;
#pragma unroll
            for (int j = 0; j < 8; j++) {
                s[j][0] = __expf(s[j][0] - mn0);
                s[j][1] = __expf(s[j][1] - mn0);
                s[j][2] = __expf(s[j][2] - mn1);
                s[j][3] = __expf(s[j][3] - mn1);
                sum0 += s[j][0] + s[j][1];
                sum1 += s[j][2] + s[j][3];
            }
            sum0 += __shfl_xor_sync(0xffffffffu, sum0, 1);
            sum0 += __shfl_xor_sync(0xffffffffu, sum0, 2);
            sum1 += __shfl_xor_sync(0xffffffffu, sum1, 1);
            sum1 += __shfl_xor_sync(0xffffffffu, sum1, 2);
            l0 = l0 * a0 + sum0;  l1 = l1 * a1 + sum1;
            m0 = mn0;  m1 = mn1;
#pragma unroll
            for (int j = 0; j < 8; j++) {
                o[j][0] *= a0; o[j][1] *= a0; o[j][2] *= a1; o[j][3] *= a1;
            }

#pragma unroll
            for (int t = 0; t < 4; t++) {
                unsigned ahi[4], alo[4];
                {
                    const float p0 = s[2 * t][0],     p1 = s[2 * t][1];
                    const float p2 = s[2 * t][2],     p3 = s[2 * t][3];
                    const float r0 = s[2 * t + 1][0], r1 = s[2 * t + 1][1];
                    const float r2 = s[2 * t + 1][2], r3 = s[2 * t + 1][3];
                    __nv_bfloat16 h0 = __float2bfloat16_rn(p0), h1 = __float2bfloat16_rn(p1);
                    __nv_bfloat16 h2 = __float2bfloat16_rn(p2), h3 = __float2bfloat16_rn(p3);
                    __nv_bfloat16 e0 = __float2bfloat16_rn(r0), e1 = __float2bfloat16_rn(r1);
                    __nv_bfloat16 e2 = __float2bfloat16_rn(r2), e3 = __float2bfloat16_rn(r3);
                    ahi[0] = pack_bf2(h0, h1); ahi[1] = pack_bf2(h2, h3);
                    ahi[2] = pack_bf2(e0, e1); ahi[3] = pack_bf2(e2, e3);
                    alo[0] = pack_bf2(__float2bfloat16_rn(p0 - __bfloat162float(h0)),
                                      __float2bfloat16_rn(p1 - __bfloat162float(h1)));
                    alo[1] = pack_bf2(__float2bfloat16_rn(p2 - __bfloat162float(h2)),
                                      __float2bfloat16_rn(p3 - __bfloat162float(h3)));
                    alo[2] = pack_bf2(__float2bfloat16_rn(r0 - __bfloat162float(e0)),
                                      __float2bfloat16_rn(r1 - __bfloat162float(e1)));
                    alo[3] = pack_bf2(__float2bfloat16_rn(r2 - __bfloat162float(e2)),
                                      __float2bfloat16_rn(r3 - __bfloat162float(e3)));
                }
#pragma unroll
                for (int j2 = 0; j2 < 4; j2++) {
                    unsigned v0, v1, v2, v3;
                    ldsm_x4_t(v0, v1, v2, v3, va + t * (16 * FROWB) + j2 * 32);
                    unsigned bA[2] = {v0, v1}, bB[2] = {v2, v3};
                    mma16816(o[2 * j2],     ahi, bA);
                    mma16816(o[2 * j2 + 1], ahi, bB);
                    mma16816(o[2 * j2],     alo, bA);
                    mma16816(o[2 * j2 + 1], alo, bB);
                }
#pragma unroll
                for (int j2 = 0; j2 < 4; j2++) {
                    unsigned v0, v1, v2, v3;
                    ldsm_x4_t(v0, v1, v2, v3,
                              va + FTILE + t * (16 * FROWB) + j2 * 32);
                    unsigned bA[2] = {v0, v1}, bB[2] = {v2, v3};
                    mma16816(o[2 * j2],     ahi, bA);
                    mma16816(o[2 * j2 + 1], ahi, bB);
                }
            }
        }
        __syncthreads();
    }

    const float i0 = 1.f / l0, i1 = 1.f / l1;
    const int tok0 = b * SEQ + q0 + warp_m + g;
    const int tok1 = tok0 + 8;
    const int colb = h * DH + 2 * c4;
#pragma unroll
    for (int j = 0; j < 8; j++) {
        split_store(g_ahi, g_alo, (size_t)tok0 * DM + colb + 8 * j,
                    o[j][0] * i0, o[j][1] * i0);
        split_store(g_ahi, g_alo, (size_t)tok1 * DM + colb + 8 * j,
                    o[j][2] * i1, o[j][3] * i1);
    }
}

// ---------------------------------------------------------------------------
extern "C" void kernel_launch(void* const* d_in, const int* in_sizes, int n_in,
                              void* d_out, int out_size)
{
    (void)in_sizes; (void)n_in; (void)out_size;
    const float* x    = (const float*)d_in[0];
    const float* Wqkv = (const float*)d_in[1];
    const float* bqkv = (const float*)d_in[2];
    const float* Wo   = (const float*)d_in[3];
    const float* bo   = (const float*)d_in[4];
    float* out = (float*)d_out;

    cudaFuncSetAttribute(tc_gemm_kernel<0>,
                         cudaFuncAttributeMaxDynamicSharedMemorySize, GEMM_SMEM);
    cudaFuncSetAttribute(tc_gemm_kernel<1>,
                         cudaFuncAttributeMaxDynamicSharedMemorySize, GEMM_SMEM);
    cudaFuncSetAttribute(flash_tc_kernel,
                         cudaFuncAttributeMaxDynamicSharedMemorySize, FLASH_SMEM);

    split_kernel<<<(TOKENS * DM / 4 + 255) / 256, 256>>>(x,    0, TOKENS * DM / 4);
    split_kernel<<<(3 * DM * DM / 4 + 255) / 256, 256>>>(Wqkv, 1, 3 * DM * DM / 4);
    split_kernel<<<(DM * DM / 4 + 255) / 256, 256>>>(Wo,       2, DM * DM / 4);

    tc_gemm_kernel<0><<<dim3(3 * DM / 128, TOKENS / 128), 256, GEMM_SMEM>>>(bqkv, nullptr);

    flash_tc_kernel<<<dim3(SEQ / 128, NH, BATCH), 256, FLASH_SMEM>>>();

    tc_gemm_kernel<1><<<dim3(DM / 128, TOKENS / 128), 256, GEMM_SMEM>>>(bo, out);
}

// round 7
// speedup vs baseline: 4.2410x; 1.4102x over previous
#include <cuda_runtime.h>
#include <cuda_fp16.h>
#include <math.h>

#define DM     1024
#define NH     16
#define DH     64
#define BATCH  4
#define SEQ    2048
#define TOKENS (BATCH * SEQ)

// ---------------------------------------------------------------------------
// Scratch (static device memory — no allocations allowed). fp16 2-term scheme.
// ---------------------------------------------------------------------------
__device__ __align__(16) __half g_xhi[TOKENS * DM];
__device__ __align__(16) __half g_xlo[TOKENS * DM];
__device__ __align__(16) __half g_wqkv_hi[3 * DM * DM];
__device__ __align__(16) __half g_wo_hi[DM * DM];
__device__ __align__(16) __half g_ahi[TOKENS * DM];
__device__ __align__(16) __half g_alo[TOKENS * DM];
__device__ __align__(16) __half g_Qhi[TOKENS * DM];   // pre-scaled by 0.125
__device__ __align__(16) __half g_Qlo[TOKENS * DM];
__device__ __align__(16) __half g_Khi[TOKENS * DM];
__device__ __align__(16) __half g_Vhi[TOKENS * DM];

// ---------------------------------------------------------------------------
// helpers
// ---------------------------------------------------------------------------
__device__ __forceinline__ unsigned smem_to_u32(const void* p) {
    unsigned a;
    asm("{ .reg .u64 t; cvta.to.shared.u64 t, %1; cvt.u32.u64 %0, t; }"
        : "=r"(a) : "l"(p));
    return a;
}

#define CP_ASYNC16(saddr, gptr) \
    asm volatile("cp.async.cg.shared.global [%0], [%1], 16;" \
                 :: "r"((unsigned)(saddr)), "l"(gptr))
#define CP_COMMIT() asm volatile("cp.async.commit_group;" ::: "memory")
#define CP_WAIT(n)  asm volatile("cp.async.wait_group %0;" :: "n"(n) : "memory")

__device__ __forceinline__ void ldsm_x4(unsigned& r0, unsigned& r1,
                                        unsigned& r2, unsigned& r3,
                                        unsigned addr) {
    asm volatile("ldmatrix.sync.aligned.m8n8.x4.shared.b16 {%0,%1,%2,%3}, [%4];"
                 : "=r"(r0), "=r"(r1), "=r"(r2), "=r"(r3) : "r"(addr));
}

__device__ __forceinline__ void ldsm_x4_t(unsigned& r0, unsigned& r1,
                                          unsigned& r2, unsigned& r3,
                                          unsigned addr) {
    asm volatile("ldmatrix.sync.aligned.m8n8.x4.trans.shared.b16 {%0,%1,%2,%3}, [%4];"
                 : "=r"(r0), "=r"(r1), "=r"(r2), "=r"(r3) : "r"(addr));
}

__device__ __forceinline__ void mma16816(float* d, const unsigned* a,
                                         const unsigned* b) {
    asm volatile(
        "mma.sync.aligned.m16n8k16.row.col.f32.f16.f16.f32 "
        "{%0,%1,%2,%3}, {%4,%5,%6,%7}, {%8,%9}, {%0,%1,%2,%3};"
        : "+f"(d[0]), "+f"(d[1]), "+f"(d[2]), "+f"(d[3])
        : "r"(a[0]), "r"(a[1]), "r"(a[2]), "r"(a[3]), "r"(b[0]), "r"(b[1]));
}

__device__ __forceinline__ unsigned pack_h2(__half a, __half b) {
    __half2 t = __halves2half2(a, b);
    return *(unsigned*)&t;
}

__device__ __forceinline__ void split_store_h(__half* hp, __half* lp,
                                              size_t idx, float a, float b) {
    __half ha = __float2half_rn(a), hb = __float2half_rn(b);
    float la = a - __half2float(ha), lb = b - __half2float(hb);
    *(unsigned*)(hp + idx) = pack_h2(ha, hb);
    *(unsigned*)(lp + idx) = pack_h2(__float2half_rn(la), __float2half_rn(lb));
}

// ---------------------------------------------------------------------------
// fp32 -> fp16 conversion kernels.
// mode 0: x -> hi/lo ; mode 1: Wqkv -> hi only ; mode 2: Wo -> hi only
// ---------------------------------------------------------------------------
__global__ void __launch_bounds__(256) split_kernel(
    const float* __restrict__ src, int mode, int n4)
{
    int i = blockIdx.x * blockDim.x + threadIdx.x;
    if (i >= n4) return;
    float4 v = ((const float4*)src)[i];
    float f[4] = {v.x, v.y, v.z, v.w};
    __half h[4];
#pragma unroll
    for (int j = 0; j < 4; j++) h[j] = __float2half_rn(f[j]);

    if (mode == 0) {
        __half l[4];
#pragma unroll
        for (int j = 0; j < 4; j++)
            l[j] = __float2half_rn(f[j] - __half2float(h[j]));
        ((unsigned*)g_xhi)[2 * i]     = pack_h2(h[0], h[1]);
        ((unsigned*)g_xhi)[2 * i + 1] = pack_h2(h[2], h[3]);
        ((unsigned*)g_xlo)[2 * i]     = pack_h2(l[0], l[1]);
        ((unsigned*)g_xlo)[2 * i + 1] = pack_h2(l[2], l[3]);
    } else {
        __half* hp = (mode == 1) ? g_wqkv_hi : g_wo_hi;
        ((unsigned*)hp)[2 * i]     = pack_h2(h[0], h[1]);
        ((unsigned*)hp)[2 * i + 1] = pack_h2(h[2], h[3]);
    }
}

// ---------------------------------------------------------------------------
// Tensor-core GEMM fp16 2-term: C = (Ahi+Alo) @ Bhi^T + bias. K=1024.
// CTA 128x128, 8 warps 64x32, BK=32, cp.async double-buffered (3 tiles/stage).
// MODE 0: -> Qhi/Qlo (scaled 0.125), Khi, Vhi in [B,H,S,DH]
// MODE 1: -> fp32 row-major Cout
// ---------------------------------------------------------------------------
#define GTILE  10240                 // 128 rows x 80B pitch
#define GSTAGE (3 * GTILE)           // Ahi|Alo|Bhi = 30720
#define GEMM_SMEM (2 * GSTAGE)       // 61440

template <int MODE>
__global__ void __launch_bounds__(256, 2) tc_gemm_kernel(
    const float* __restrict__ bias, float* __restrict__ Cout)
{
    extern __shared__ __align__(16) char gsm[];

    const int tid  = threadIdx.x;
    const int lane = tid & 31;
    const int wid  = tid >> 5;
    const int n0 = blockIdx.x << 7;
    const int m0 = blockIdx.y << 7;
    const int warp_m = (wid & 1) << 6;
    const int warp_n = (wid >> 1) << 5;
    const unsigned sbase = smem_to_u32(gsm);

    const __half* Ahi = (MODE == 0) ? g_xhi : g_ahi;
    const __half* Alo = (MODE == 0) ? g_xlo : g_alo;
    const __half* Bhi = (MODE == 0) ? g_wqkv_hi : g_wo_hi;

    // staging: each thread covers rows (tid>>2) and (tid>>2)+64, quad (tid&3)
    const int rowA = tid >> 2;
    const int quad = tid & 3;
    const __half* pA0h = Ahi + (size_t)(m0 + rowA) * DM + quad * 8;
    const __half* pA1h = pA0h + (size_t)64 * DM;
    const __half* pA0l = Alo + (size_t)(m0 + rowA) * DM + quad * 8;
    const __half* pA1l = pA0l + (size_t)64 * DM;
    const __half* pB0  = Bhi + (size_t)(n0 + rowA) * DM + quad * 8;
    const __half* pB1  = pB0 + (size_t)64 * DM;
    const unsigned so0 = rowA * 80 + quad * 16;
    const unsigned so1 = so0 + 64 * 80;

    // fragment lane addressing
    const unsigned aHi0 = sbase + (warp_m + (lane & 15)) * 80 + ((lane >> 4) << 4);
    const unsigned bRow = warp_n + ((lane >> 4) << 3) + (lane & 7);
    const unsigned bHi0 = sbase + 2 * GTILE + bRow * 80 + (((lane >> 3) & 1) << 4);

    float acc[4][4][4] = {};

    // prologue: chunk 0 -> stage 0
    {
        CP_ASYNC16(sbase + so0, pA0h);
        CP_ASYNC16(sbase + so1, pA1h);
        CP_ASYNC16(sbase + GTILE + so0, pA0l);
        CP_ASYNC16(sbase + GTILE + so1, pA1l);
        CP_ASYNC16(sbase + 2 * GTILE + so0, pB0);
        CP_ASYNC16(sbase + 2 * GTILE + so1, pB1);
        CP_COMMIT();
    }

    for (int c = 0; c < 32; c++) {
        if (c + 1 < 32) {
            const unsigned st = sbase + ((c + 1) & 1) * GSTAGE;
            const int kc = (c + 1) * 32;
            CP_ASYNC16(st + so0, pA0h + kc);
            CP_ASYNC16(st + so1, pA1h + kc);
            CP_ASYNC16(st + GTILE + so0, pA0l + kc);
            CP_ASYNC16(st + GTILE + so1, pA1l + kc);
            CP_ASYNC16(st + 2 * GTILE + so0, pB0 + kc);
            CP_ASYNC16(st + 2 * GTILE + so1, pB1 + kc);
            CP_COMMIT();
            CP_WAIT(1);
        } else {
            CP_WAIT(0);
        }
        __syncthreads();

        const unsigned stof = (c & 1) * GSTAGE;
        const unsigned aHi = aHi0 + stof;
        const unsigned aLo = aHi + GTILE;
        const unsigned bHi = bHi0 + stof;

#pragma unroll
        for (int ks2 = 0; ks2 < 2; ks2++) {
            const unsigned kb = ks2 << 5;
            unsigned a_hi[4][4], a_lo[4][4], bf[4][2];
#pragma unroll
            for (int i = 0; i < 4; i++)
                ldsm_x4(a_hi[i][0], a_hi[i][1], a_hi[i][2], a_hi[i][3],
                        aHi + i * (16 * 80) + kb);
#pragma unroll
            for (int i = 0; i < 4; i++)
                ldsm_x4(a_lo[i][0], a_lo[i][1], a_lo[i][2], a_lo[i][3],
                        aLo + i * (16 * 80) + kb);
            ldsm_x4(bf[0][0], bf[0][1], bf[1][0], bf[1][1], bHi + kb);
            ldsm_x4(bf[2][0], bf[2][1], bf[3][0], bf[3][1], bHi + 16 * 80 + kb);
#pragma unroll
            for (int i = 0; i < 4; i++)
#pragma unroll
                for (int j = 0; j < 4; j++)
                    mma16816(acc[i][j], a_hi[i], bf[j]);
#pragma unroll
            for (int i = 0; i < 4; i++)
#pragma unroll
                for (int j = 0; j < 4; j++)
                    mma16816(acc[i][j], a_lo[i], bf[j]);
        }
        __syncthreads();
    }

    const int g = lane >> 2;
    const int c = lane & 3;
#pragma unroll
    for (int i = 0; i < 4; i++) {
#pragma unroll
        for (int j = 0; j < 4; j++) {
            const int rm = m0 + warp_m + i * 16 + g;
            const int cn = n0 + warp_n + j * 8 + 2 * c;
            const float2 bv = *(const float2*)(bias + cn);
            float v00 = acc[i][j][0] + bv.x, v01 = acc[i][j][1] + bv.y;
            float v10 = acc[i][j][2] + bv.x, v11 = acc[i][j][3] + bv.y;
            if (MODE == 0) {
                const int which = cn >> 10;           // 0=Q,1=K,2=V
                const int head  = (cn & 1023) >> 6;
                const int hcol  = cn & 63;
                const int b0r = rm >> 11, s0 = rm & 2047;
                const int b1r = (rm + 8) >> 11, s1 = (rm + 8) & 2047;
                const size_t i0 = (((size_t)(b0r * NH + head)) * SEQ + s0) * DH + hcol;
                const size_t i1 = (((size_t)(b1r * NH + head)) * SEQ + s1) * DH + hcol;
                if (which == 0) {
                    split_store_h(g_Qhi, g_Qlo, i0, v00 * 0.125f, v01 * 0.125f);
                    split_store_h(g_Qhi, g_Qlo, i1, v10 * 0.125f, v11 * 0.125f);
                } else {
                    __half* hp = (which == 1) ? g_Khi : g_Vhi;
                    *(unsigned*)(hp + i0) =
                        pack_h2(__float2half_rn(v00), __float2half_rn(v01));
                    *(unsigned*)(hp + i1) =
                        pack_h2(__float2half_rn(v10), __float2half_rn(v11));
                }
            } else {
                *(float2*)(Cout + (size_t)rm * DM + cn) = make_float2(v00, v01);
                *(float2*)(Cout + (size_t)(rm + 8) * DM + cn) = make_float2(v10, v11);
            }
        }
    }
}

// ---------------------------------------------------------------------------
// Tensor-core causal flash attention, fp16 2-term.
// S = (Qhi+Qlo)·Khi^T ; O += (Phi+Plo)·Vhi.
// CTA: 128 q-rows of one (b,h); 8 warps x 16 rows; K-tiles of 64.
// cp.async double-buffered Khi|Vhi tiles.
// Q staging: Qhi occupies [0, 2*FTILE) (128 rows!), Qlo at [2*FTILE, 4*FTILE).
// ---------------------------------------------------------------------------
#define FROWB 144
#define FTILE (64 * FROWB)          // 9216 (64-row tile)
#define FSTAGE (2 * FTILE)          // Khi|Vhi = 18432
#define FLASH_SMEM (2 * FSTAGE)     // 36864

__global__ void __launch_bounds__(256) flash_tc_kernel()
{
    extern __shared__ __align__(16) char fsm[];

    const int tid  = threadIdx.x;
    const int lane = tid & 31;
    const int wid  = tid >> 5;
    const int warp_m = wid << 4;
    const int qt = (SEQ / 128 - 1) - blockIdx.x;
    const int h  = blockIdx.y;
    const int b  = blockIdx.z;
    const int q0 = qt << 7;
    const int bh = b * NH + h;
    const size_t base = (size_t)bh * SEQ * DH;
    const unsigned sb = smem_to_u32(fsm);

    // ---- stage Q hi/lo (128 rows each: hi at 0, lo at 2*FTILE) ----
    {
        const __half* qh = g_Qhi + base + (size_t)q0 * DH;
        const __half* ql = g_Qlo + base + (size_t)q0 * DH;
#pragma unroll
        for (int r = 0; r < 4; r++) {
            const int cc = tid + (r << 8);
            const int row = cc >> 3, ch = cc & 7;
            *(uint4*)(fsm + row * FROWB + ch * 16) =
                *(const uint4*)(qh + row * DH + ch * 8);
            *(uint4*)(fsm + 2 * FTILE + row * FROWB + ch * 16) =
                *(const uint4*)(ql + row * DH + ch * 8);
        }
    }
    __syncthreads();
    unsigned qf_hi[4][4], qf_lo[4][4];
    {
        const unsigned qa = sb + (warp_m + (lane & 15)) * FROWB + ((lane >> 4) << 4);
#pragma unroll
        for (int t = 0; t < 4; t++) {
            ldsm_x4(qf_hi[t][0], qf_hi[t][1], qf_hi[t][2], qf_hi[t][3], qa + t * 32);
            ldsm_x4(qf_lo[t][0], qf_lo[t][1], qf_lo[t][2], qf_lo[t][3],
                    qa + 2 * FTILE + t * 32);
        }
    }
    __syncthreads();

    float o[8][4] = {};
    float m0 = -1e30f, m1 = -1e30f, l0 = 0.f, l1 = 0.f;
    const int g  = lane >> 2;
    const int c4 = lane & 3;
    const int row0 = q0 + warp_m + g;
    const int row1 = row0 + 8;

    const unsigned ka0 = sb + ((lane & 7) + ((lane >> 4) << 3)) * FROWB
                            + (((lane >> 3) & 1) << 4);
    const unsigned va0 = sb + FTILE
                            + ((lane & 7) + (((lane >> 3) & 1) << 3)) * FROWB
                            + ((lane >> 4) << 4);

    // staging map: per tile, 2 slots/thread
    const int srow = tid >> 3, sch = tid & 7;
    const unsigned sso = srow * FROWB + sch * 16;
    const unsigned sgo = srow * DH + sch * 8;

    const int nkt = (q0 >> 6) + 2;

    // prologue: tile 0 -> stage 0
    {
        const __half* pk = g_Khi + base;
        const __half* pv = g_Vhi + base;
#pragma unroll
        for (int r = 0; r < 2; r++) {
            const unsigned so = sso + r * (32 * FROWB);
            const unsigned go = sgo + r * (32 * DH);
            CP_ASYNC16(sb + so, pk + go);
            CP_ASYNC16(sb + FTILE + so, pv + go);
        }
        CP_COMMIT();
    }

    for (int kt = 0; kt < nkt; kt++) {
        const int k0 = kt << 6;
        if (kt + 1 < nkt) {
            const size_t nb = base + (size_t)((kt + 1) << 6) * DH;
            const unsigned st = sb + ((kt + 1) & 1) * FSTAGE;
            const __half* pk = g_Khi + nb;
            const __half* pv = g_Vhi + nb;
#pragma unroll
            for (int r = 0; r < 2; r++) {
                const unsigned so = sso + r * (32 * FROWB);
                const unsigned go = sgo + r * (32 * DH);
                CP_ASYNC16(st + so, pk + go);
                CP_ASYNC16(st + FTILE + so, pv + go);
            }
            CP_COMMIT();
            CP_WAIT(1);
        } else {
            CP_WAIT(0);
        }
        __syncthreads();

        if (k0 <= q0 + warp_m + 15) {
            const unsigned stof = (kt & 1) * FSTAGE;
            const unsigned ka = ka0 + stof;
            const unsigned va = va0 + stof;

            float s[8][4];
#pragma unroll
            for (int j = 0; j < 8; j++)
#pragma unroll
                for (int x = 0; x < 4; x++) s[j][x] = 0.f;

#pragma unroll
            for (int t = 0; t < 4; t++) {
                unsigned kf[8][2];
#pragma unroll
                for (int jp = 0; jp < 4; jp++)
                    ldsm_x4(kf[2 * jp][0], kf[2 * jp][1],
                            kf[2 * jp + 1][0], kf[2 * jp + 1][1],
                            ka + jp * (16 * FROWB) + t * 32);
#pragma unroll
                for (int j = 0; j < 8; j++) mma16816(s[j], qf_hi[t], kf[j]);
#pragma unroll
                for (int j = 0; j < 8; j++) mma16816(s[j], qf_lo[t], kf[j]);
            }

            if (k0 + 63 > q0 + warp_m) {
#pragma unroll
                for (int j = 0; j < 8; j++) {
                    const int col = k0 + 8 * j + 2 * c4;
                    if (col     > row0) s[j][0] = -1e30f;
                    if (col + 1 > row0) s[j][1] = -1e30f;
                    if (col     > row1) s[j][2] = -1e30f;
                    if (col + 1 > row1) s[j][3] = -1e30f;
                }
            }

            float rx0 = -1e30f, rx1 = -1e30f;
#pragma unroll
            for (int j = 0; j < 8; j++) {
                rx0 = fmaxf(rx0, fmaxf(s[j][0], s[j][1]));
                rx1 = fmaxf(rx1, fmaxf(s[j][2], s[j][3]));
            }
            rx0 = fmaxf(rx0, __shfl_xor_sync(0xffffffffu, rx0, 1));
            rx0 = fmaxf(rx0, __shfl_xor_sync(0xffffffffu, rx0, 2));
            rx1 = fmaxf(rx1, __shfl_xor_sync(0xffffffffu, rx1, 1));
            rx1 = fmaxf(rx1, __shfl_xor_sync(0xffffffffu, rx1, 2));
            const float mn0 = fmaxf(m0, rx0), mn1 = fmaxf(m1, rx1);
            const float a0 = __expf(m0 - mn0), a1 = __expf(m1 - mn1);
            float sum0 = 0.f, sum1 = 0.f;
#pragma unroll
            for (int j = 0; j < 8; j++) {
                s[j][0] = __expf(s[j][0] - mn0);
                s[j][1] = __expf(s[j][1] - mn0);
                s[j][2] = __expf(s[j][2] - mn1);
                s[j][3] = __expf(s[j][3] - mn1);
                sum0 += s[j][0] + s[j][1];
                sum1 += s[j][2] + s[j][3];
            }
            sum0 += __shfl_xor_sync(0xffffffffu, sum0, 1);
            sum0 += __shfl_xor_sync(0xffffffffu, sum0, 2);
            sum1 += __shfl_xor_sync(0xffffffffu, sum1, 1);
            sum1 += __shfl_xor_sync(0xffffffffu, sum1, 2);
            l0 = l0 * a0 + sum0;  l1 = l1 * a1 + sum1;
            m0 = mn0;  m1 = mn1;
#pragma unroll
            for (int j = 0; j < 8; j++) {
                o[j][0] *= a0; o[j][1] *= a0; o[j][2] *= a1; o[j][3] *= a1;
            }

#pragma unroll
            for (int t = 0; t < 4; t++) {
                unsigned ahi[4], alo[4];
                {
                    const float p0 = s[2 * t][0],     p1 = s[2 * t][1];
                    const float p2 = s[2 * t][2],     p3 = s[2 * t][3];
                    const float r0 = s[2 * t + 1][0], r1 = s[2 * t + 1][1];
                    const float r2 = s[2 * t + 1][2], r3 = s[2 * t + 1][3];
                    __half h0 = __float2half_rn(p0), h1 = __float2half_rn(p1);
                    __half h2 = __float2half_rn(p2), h3 = __float2half_rn(p3);
                    __half e0 = __float2half_rn(r0), e1 = __float2half_rn(r1);
                    __half e2 = __float2half_rn(r2), e3 = __float2half_rn(r3);
                    ahi[0] = pack_h2(h0, h1); ahi[1] = pack_h2(h2, h3);
                    ahi[2] = pack_h2(e0, e1); ahi[3] = pack_h2(e2, e3);
                    alo[0] = pack_h2(__float2half_rn(p0 - __half2float(h0)),
                                     __float2half_rn(p1 - __half2float(h1)));
                    alo[1] = pack_h2(__float2half_rn(p2 - __half2float(h2)),
                                     __float2half_rn(p3 - __half2float(h3)));
                    alo[2] = pack_h2(__float2half_rn(r0 - __half2float(e0)),
                                     __float2half_rn(r1 - __half2float(e1)));
                    alo[3] = pack_h2(__float2half_rn(r2 - __half2float(e2)),
                                     __float2half_rn(r3 - __half2float(e3)));
                }
#pragma unroll
                for (int j2 = 0; j2 < 4; j2++) {
                    unsigned v0, v1, v2, v3;
                    ldsm_x4_t(v0, v1, v2, v3, va + t * (16 * FROWB) + j2 * 32);
                    unsigned bA[2] = {v0, v1}, bB[2] = {v2, v3};
                    mma16816(o[2 * j2],     ahi, bA);
                    mma16816(o[2 * j2 + 1], ahi, bB);
                    mma16816(o[2 * j2],     alo, bA);
                    mma16816(o[2 * j2 + 1], alo, bB);
                }
            }
        }
        __syncthreads();
    }

    // epilogue: normalize, split-store to g_ahi/g_alo [B,S,DM]
    const float i0 = 1.f / l0, i1 = 1.f / l1;
    const int tok0 = b * SEQ + q0 + warp_m + g;
    const int tok1 = tok0 + 8;
    const int colb = h * DH + 2 * c4;
#pragma unroll
    for (int j = 0; j < 8; j++) {
        split_store_h(g_ahi, g_alo, (size_t)tok0 * DM + colb + 8 * j,
                      o[j][0] * i0, o[j][1] * i0);
        split_store_h(g_ahi, g_alo, (size_t)tok1 * DM + colb + 8 * j,
                      o[j][2] * i1, o[j][3] * i1);
    }
}

// ---------------------------------------------------------------------------
extern "C" void kernel_launch(void* const* d_in, const int* in_sizes, int n_in,
                              void* d_out, int out_size)
{
    (void)in_sizes; (void)n_in; (void)out_size;
    const float* x    = (const float*)d_in[0];
    const float* Wqkv = (const float*)d_in[1];
    const float* bqkv = (const float*)d_in[2];
    const float* Wo   = (const float*)d_in[3];
    const float* bo   = (const float*)d_in[4];
    float* out = (float*)d_out;

    cudaFuncSetAttribute(tc_gemm_kernel<0>,
                         cudaFuncAttributeMaxDynamicSharedMemorySize, GEMM_SMEM);
    cudaFuncSetAttribute(tc_gemm_kernel<1>,
                         cudaFuncAttributeMaxDynamicSharedMemorySize, GEMM_SMEM);
    cudaFuncSetAttribute(flash_tc_kernel,
                         cudaFuncAttributeMaxDynamicSharedMemorySize, FLASH_SMEM);

    split_kernel<<<(TOKENS * DM / 4 + 255) / 256, 256>>>(x,    0, TOKENS * DM / 4);
    split_kernel<<<(3 * DM * DM / 4 + 255) / 256, 256>>>(Wqkv, 1, 3 * DM * DM / 4);
    split_kernel<<<(DM * DM / 4 + 255) / 256, 256>>>(Wo,       2, DM * DM / 4);

    tc_gemm_kernel<0><<<dim3(3 * DM / 128, TOKENS / 128), 256, GEMM_SMEM>>>(bqkv, nullptr);

    flash_tc_kernel<<<dim3(SEQ / 128, NH, BATCH), 256, FLASH_SMEM>>>();

    tc_gemm_kernel<1><<<dim3(DM / 128, TOKENS / 128), 256, GEMM_SMEM>>>(bo, out);
}

// round 8
// speedup vs baseline: 4.6354x; 1.0930x over previous
#include <cuda_runtime.h>
#include <cuda_fp16.h>
#include <math.h>

#define DM     1024
#define NH     16
#define DH     64
#define BATCH  4
#define SEQ    2048
#define TOKENS (BATCH * SEQ)

// ---------------------------------------------------------------------------
// Scratch (static device memory — no allocations allowed). fp16 2-term scheme.
// ---------------------------------------------------------------------------
__device__ __align__(16) __half g_xhi[TOKENS * DM];
__device__ __align__(16) __half g_xlo[TOKENS * DM];
__device__ __align__(16) __half g_wqkv_hi[3 * DM * DM];
__device__ __align__(16) __half g_wo_hi[DM * DM];
__device__ __align__(16) __half g_ahi[TOKENS * DM];
__device__ __align__(16) __half g_alo[TOKENS * DM];
__device__ __align__(16) __half g_Qhi[TOKENS * DM];   // pre-scaled by 0.125
__device__ __align__(16) __half g_Qlo[TOKENS * DM];
__device__ __align__(16) __half g_Khi[TOKENS * DM];
__device__ __align__(16) __half g_Vhi[TOKENS * DM];

// ---------------------------------------------------------------------------
// helpers
// ---------------------------------------------------------------------------
__device__ __forceinline__ unsigned smem_to_u32(const void* p) {
    unsigned a;
    asm("{ .reg .u64 t; cvta.to.shared.u64 t, %1; cvt.u32.u64 %0, t; }"
        : "=r"(a) : "l"(p));
    return a;
}

#define CP_ASYNC16(saddr, gptr) \
    asm volatile("cp.async.cg.shared.global [%0], [%1], 16;" \
                 :: "r"((unsigned)(saddr)), "l"(gptr))
#define CP_COMMIT() asm volatile("cp.async.commit_group;" ::: "memory")
#define CP_WAIT(n)  asm volatile("cp.async.wait_group %0;" :: "n"(n) : "memory")

__device__ __forceinline__ void ldsm_x4(unsigned& r0, unsigned& r1,
                                        unsigned& r2, unsigned& r3,
                                        unsigned addr) {
    asm volatile("ldmatrix.sync.aligned.m8n8.x4.shared.b16 {%0,%1,%2,%3}, [%4];"
                 : "=r"(r0), "=r"(r1), "=r"(r2), "=r"(r3) : "r"(addr));
}

__device__ __forceinline__ void ldsm_x4_t(unsigned& r0, unsigned& r1,
                                          unsigned& r2, unsigned& r3,
                                          unsigned addr) {
    asm volatile("ldmatrix.sync.aligned.m8n8.x4.trans.shared.b16 {%0,%1,%2,%3}, [%4];"
                 : "=r"(r0), "=r"(r1), "=r"(r2), "=r"(r3) : "r"(addr));
}

__device__ __forceinline__ void mma16816(float* d, const unsigned* a,
                                         const unsigned* b) {
    asm volatile(
        "mma.sync.aligned.m16n8k16.row.col.f32.f16.f16.f32 "
        "{%0,%1,%2,%3}, {%4,%5,%6,%7}, {%8,%9}, {%0,%1,%2,%3};"
        : "+f"(d[0]), "+f"(d[1]), "+f"(d[2]), "+f"(d[3])
        : "r"(a[0]), "r"(a[1]), "r"(a[2]), "r"(a[3]), "r"(b[0]), "r"(b[1]));
}

__device__ __forceinline__ unsigned pack_h2(__half a, __half b) {
    __half2 t = __halves2half2(a, b);
    return *(unsigned*)&t;
}

__device__ __forceinline__ void split_store_h(__half* hp, __half* lp,
                                              size_t idx, float a, float b) {
    __half ha = __float2half_rn(a), hb = __float2half_rn(b);
    float la = a - __half2float(ha), lb = b - __half2float(hb);
    *(unsigned*)(hp + idx) = pack_h2(ha, hb);
    *(unsigned*)(lp + idx) = pack_h2(__float2half_rn(la), __float2half_rn(lb));
}

// ---------------------------------------------------------------------------
// fp32 -> fp16 conversion kernels.
// mode 0: x -> hi/lo ; mode 1: Wqkv -> hi only ; mode 2: Wo -> hi only
// ---------------------------------------------------------------------------
__global__ void __launch_bounds__(256) split_kernel(
    const float* __restrict__ src, int mode, int n4)
{
    int i = blockIdx.x * blockDim.x + threadIdx.x;
    if (i >= n4) return;
    float4 v = ((const float4*)src)[i];
    float f[4] = {v.x, v.y, v.z, v.w};
    __half h[4];
#pragma unroll
    for (int j = 0; j < 4; j++) h[j] = __float2half_rn(f[j]);

    if (mode == 0) {
        __half l[4];
#pragma unroll
        for (int j = 0; j < 4; j++)
            l[j] = __float2half_rn(f[j] - __half2float(h[j]));
        ((unsigned*)g_xhi)[2 * i]     = pack_h2(h[0], h[1]);
        ((unsigned*)g_xhi)[2 * i + 1] = pack_h2(h[2], h[3]);
        ((unsigned*)g_xlo)[2 * i]     = pack_h2(l[0], l[1]);
        ((unsigned*)g_xlo)[2 * i + 1] = pack_h2(l[2], l[3]);
    } else {
        __half* hp = (mode == 1) ? g_wqkv_hi : g_wo_hi;
        ((unsigned*)hp)[2 * i]     = pack_h2(h[0], h[1]);
        ((unsigned*)hp)[2 * i + 1] = pack_h2(h[2], h[3]);
    }
}

// ---------------------------------------------------------------------------
// Tensor-core GEMM fp16 2-term: C = (Ahi+Alo) @ Bhi^T + bias. K=1024.
// CTA 128x128, 8 warps each 32x64 (warp_m 0..96, warp_n 0/64), BK=32.
// 3-stage cp.async pipeline, ONE __syncthreads per chunk.
// MODE 0: -> Qhi/Qlo (scaled 0.125), Khi, Vhi in [B,H,S,DH]
// MODE 1: -> fp32 row-major Cout
// ---------------------------------------------------------------------------
#define GTILE  10240                 // 128 rows x 80B pitch
#define GSTAGE (3 * GTILE)           // Ahi|Alo|Bhi = 30720
#define GEMM_SMEM (3 * GSTAGE)       // 92160 (3 stages)

template <int MODE>
__global__ void __launch_bounds__(256, 2) tc_gemm_kernel(
    const float* __restrict__ bias, float* __restrict__ Cout)
{
    extern __shared__ __align__(16) char gsm[];

    const int tid  = threadIdx.x;
    const int lane = tid & 31;
    const int wid  = tid >> 5;
    const int n0 = blockIdx.x << 7;
    const int m0 = blockIdx.y << 7;
    const int warp_m = (wid & 3) << 5;   // 0,32,64,96
    const int warp_n = (wid >> 2) << 6;  // 0,64
    const unsigned sbase = smem_to_u32(gsm);

    const __half* Ahi = (MODE == 0) ? g_xhi : g_ahi;
    const __half* Alo = (MODE == 0) ? g_xlo : g_alo;
    const __half* Bhi = (MODE == 0) ? g_wqkv_hi : g_wo_hi;

    // staging: each thread covers rows (tid>>2) and (tid>>2)+64, quad (tid&3)
    const int rowA = tid >> 2;
    const int quad = tid & 3;
    const __half* pA0h = Ahi + (size_t)(m0 + rowA) * DM + quad * 8;
    const __half* pA1h = pA0h + (size_t)64 * DM;
    const __half* pA0l = Alo + (size_t)(m0 + rowA) * DM + quad * 8;
    const __half* pA1l = pA0l + (size_t)64 * DM;
    const __half* pB0  = Bhi + (size_t)(n0 + rowA) * DM + quad * 8;
    const __half* pB1  = pB0 + (size_t)64 * DM;
    const unsigned so0 = rowA * 80 + quad * 16;
    const unsigned so1 = so0 + 64 * 80;

    // fragment lane addressing (stage offset added per chunk)
    const unsigned aHi0 = sbase + (warp_m + (lane & 15)) * 80 + ((lane >> 4) << 4);
    const unsigned bRow = warp_n + ((lane >> 4) << 3) + (lane & 7);
    const unsigned bHi0 = sbase + 2 * GTILE + bRow * 80 + (((lane >> 3) & 1) << 4);

    float acc[2][8][4] = {};

    // prologue: chunks 0,1 -> stages 0,1
#pragma unroll
    for (int p = 0; p < 2; p++) {
        const unsigned st = sbase + p * GSTAGE;
        const int kc = p * 32;
        CP_ASYNC16(st + so0, pA0h + kc);
        CP_ASYNC16(st + so1, pA1h + kc);
        CP_ASYNC16(st + GTILE + so0, pA0l + kc);
        CP_ASYNC16(st + GTILE + so1, pA1l + kc);
        CP_ASYNC16(st + 2 * GTILE + so0, pB0 + kc);
        CP_ASYNC16(st + 2 * GTILE + so1, pB1 + kc);
        CP_COMMIT();
    }

    int stage = 0;
    for (int c = 0; c < 32; c++) {
        if (c <= 29) { CP_WAIT(1); } else { CP_WAIT(0); }
        __syncthreads();

        const unsigned stof = (unsigned)stage * GSTAGE;
        const unsigned aHi = aHi0 + stof;
        const unsigned aLo = aHi + GTILE;
        const unsigned bHi = bHi0 + stof;

#pragma unroll
        for (int ks2 = 0; ks2 < 2; ks2++) {
            const unsigned kb = ks2 << 5;
            unsigned a_hi[2][4], a_lo[2][4], bf[8][2];
#pragma unroll
            for (int i = 0; i < 2; i++)
                ldsm_x4(a_hi[i][0], a_hi[i][1], a_hi[i][2], a_hi[i][3],
                        aHi + i * (16 * 80) + kb);
#pragma unroll
            for (int i = 0; i < 2; i++)
                ldsm_x4(a_lo[i][0], a_lo[i][1], a_lo[i][2], a_lo[i][3],
                        aLo + i * (16 * 80) + kb);
#pragma unroll
            for (int jp = 0; jp < 4; jp++)
                ldsm_x4(bf[2 * jp][0], bf[2 * jp][1],
                        bf[2 * jp + 1][0], bf[2 * jp + 1][1],
                        bHi + jp * (16 * 80) + kb);
#pragma unroll
            for (int i = 0; i < 2; i++)
#pragma unroll
                for (int j = 0; j < 8; j++)
                    mma16816(acc[i][j], a_hi[i], bf[j]);
#pragma unroll
            for (int i = 0; i < 2; i++)
#pragma unroll
                for (int j = 0; j < 8; j++)
                    mma16816(acc[i][j], a_lo[i], bf[j]);
        }

        // issue chunk c+2 into the stage just freed at iteration c-1
        if (c + 2 < 32) {
            const int ws = (stage + 2) % 3;
            const unsigned st = sbase + (unsigned)ws * GSTAGE;
            const int kc = (c + 2) * 32;
            CP_ASYNC16(st + so0, pA0h + kc);
            CP_ASYNC16(st + so1, pA1h + kc);
            CP_ASYNC16(st + GTILE + so0, pA0l + kc);
            CP_ASYNC16(st + GTILE + so1, pA1l + kc);
            CP_ASYNC16(st + 2 * GTILE + so0, pB0 + kc);
            CP_ASYNC16(st + 2 * GTILE + so1, pB1 + kc);
            CP_COMMIT();
        }
        stage = (stage + 1) % 3;
    }

    const int g = lane >> 2;
    const int c = lane & 3;
#pragma unroll
    for (int i = 0; i < 2; i++) {
#pragma unroll
        for (int j = 0; j < 8; j++) {
            const int rm = m0 + warp_m + i * 16 + g;
            const int cn = n0 + warp_n + j * 8 + 2 * c;
            const float2 bv = *(const float2*)(bias + cn);
            float v00 = acc[i][j][0] + bv.x, v01 = acc[i][j][1] + bv.y;
            float v10 = acc[i][j][2] + bv.x, v11 = acc[i][j][3] + bv.y;
            if (MODE == 0) {
                const int which = cn >> 10;           // 0=Q,1=K,2=V
                const int head  = (cn & 1023) >> 6;
                const int hcol  = cn & 63;
                const int b0r = rm >> 11, s0 = rm & 2047;
                const int b1r = (rm + 8) >> 11, s1 = (rm + 8) & 2047;
                const size_t i0 = (((size_t)(b0r * NH + head)) * SEQ + s0) * DH + hcol;
                const size_t i1 = (((size_t)(b1r * NH + head)) * SEQ + s1) * DH + hcol;
                if (which == 0) {
                    split_store_h(g_Qhi, g_Qlo, i0, v00 * 0.125f, v01 * 0.125f);
                    split_store_h(g_Qhi, g_Qlo, i1, v10 * 0.125f, v11 * 0.125f);
                } else {
                    __half* hp = (which == 1) ? g_Khi : g_Vhi;
                    *(unsigned*)(hp + i0) =
                        pack_h2(__float2half_rn(v00), __float2half_rn(v01));
                    *(unsigned*)(hp + i1) =
                        pack_h2(__float2half_rn(v10), __float2half_rn(v11));
                }
            } else {
                *(float2*)(Cout + (size_t)rm * DM + cn) = make_float2(v00, v01);
                *(float2*)(Cout + (size_t)(rm + 8) * DM + cn) = make_float2(v10, v11);
            }
        }
    }
}

// ---------------------------------------------------------------------------
// Tensor-core causal flash attention, fp16 2-term (unchanged from round 7).
// Q staging: Qhi occupies [0, 2*FTILE) (128 rows), Qlo at [2*FTILE, 4*FTILE).
// ---------------------------------------------------------------------------
#define FROWB 144
#define FTILE (64 * FROWB)          // 9216 (64-row tile)
#define FSTAGE (2 * FTILE)          // Khi|Vhi = 18432
#define FLASH_SMEM (2 * FSTAGE)     // 36864

__global__ void __launch_bounds__(256) flash_tc_kernel()
{
    extern __shared__ __align__(16) char fsm[];

    const int tid  = threadIdx.x;
    const int lane = tid & 31;
    const int wid  = tid >> 5;
    const int warp_m = wid << 4;
    const int qt = (SEQ / 128 - 1) - blockIdx.x;
    const int h  = blockIdx.y;
    const int b  = blockIdx.z;
    const int q0 = qt << 7;
    const int bh = b * NH + h;
    const size_t base = (size_t)bh * SEQ * DH;
    const unsigned sb = smem_to_u32(fsm);

    // ---- stage Q hi/lo (128 rows each: hi at 0, lo at 2*FTILE) ----
    {
        const __half* qh = g_Qhi + base + (size_t)q0 * DH;
        const __half* ql = g_Qlo + base + (size_t)q0 * DH;
#pragma unroll
        for (int r = 0; r < 4; r++) {
            const int cc = tid + (r << 8);
            const int row = cc >> 3, ch = cc & 7;
            *(uint4*)(fsm + row * FROWB + ch * 16) =
                *(const uint4*)(qh + row * DH + ch * 8);
            *(uint4*)(fsm + 2 * FTILE + row * FROWB + ch * 16) =
                *(const uint4*)(ql + row * DH + ch * 8);
        }
    }
    __syncthreads();
    unsigned qf_hi[4][4], qf_lo[4][4];
    {
        const unsigned qa = sb + (warp_m + (lane & 15)) * FROWB + ((lane >> 4) << 4);
#pragma unroll
        for (int t = 0; t < 4; t++) {
            ldsm_x4(qf_hi[t][0], qf_hi[t][1], qf_hi[t][2], qf_hi[t][3], qa + t * 32);
            ldsm_x4(qf_lo[t][0], qf_lo[t][1], qf_lo[t][2], qf_lo[t][3],
                    qa + 2 * FTILE + t * 32);
        }
    }
    __syncthreads();

    float o[8][4] = {};
    float m0 = -1e30f, m1 = -1e30f, l0 = 0.f, l1 = 0.f;
    const int g  = lane >> 2;
    const int c4 = lane & 3;
    const int row0 = q0 + warp_m + g;
    const int row1 = row0 + 8;

    const unsigned ka0 = sb + ((lane & 7) + ((lane >> 4) << 3)) * FROWB
                            + (((lane >> 3) & 1) << 4);
    const unsigned va0 = sb + FTILE
                            + ((lane & 7) + (((lane >> 3) & 1) << 3)) * FROWB
                            + ((lane >> 4) << 4);

    const int srow = tid >> 3, sch = tid & 7;
    const unsigned sso = srow * FROWB + sch * 16;
    const unsigned sgo = srow * DH + sch * 8;

    const int nkt = (q0 >> 6) + 2;

    // prologue: tile 0 -> stage 0
    {
        const __half* pk = g_Khi + base;
        const __half* pv = g_Vhi + base;
#pragma unroll
        for (int r = 0; r < 2; r++) {
            const unsigned so = sso + r * (32 * FROWB);
            const unsigned go = sgo + r * (32 * DH);
            CP_ASYNC16(sb + so, pk + go);
            CP_ASYNC16(sb + FTILE + so, pv + go);
        }
        CP_COMMIT();
    }

    for (int kt = 0; kt < nkt; kt++) {
        const int k0 = kt << 6;
        if (kt + 1 < nkt) {
            const size_t nb = base + (size_t)((kt + 1) << 6) * DH;
            const unsigned st = sb + ((kt + 1) & 1) * FSTAGE;
            const __half* pk = g_Khi + nb;
            const __half* pv = g_Vhi + nb;
#pragma unroll
            for (int r = 0; r < 2; r++) {
                const unsigned so = sso + r * (32 * FROWB);
                const unsigned go = sgo + r * (32 * DH);
                CP_ASYNC16(st + so, pk + go);
                CP_ASYNC16(st + FTILE + so, pv + go);
            }
            CP_COMMIT();
            CP_WAIT(1);
        } else {
            CP_WAIT(0);
        }
        __syncthreads();

        if (k0 <= q0 + warp_m + 15) {
            const unsigned stof = (kt & 1) * FSTAGE;
            const unsigned ka = ka0 + stof;
            const unsigned va = va0 + stof;

            float s[8][4];
#pragma unroll
            for (int j = 0; j < 8; j++)
#pragma unroll
                for (int x = 0; x < 4; x++) s[j][x] = 0.f;

#pragma unroll
            for (int t = 0; t < 4; t++) {
                unsigned kf[8][2];
#pragma unroll
                for (int jp = 0; jp < 4; jp++)
                    ldsm_x4(kf[2 * jp][0], kf[2 * jp][1],
                            kf[2 * jp + 1][0], kf[2 * jp + 1][1],
                            ka + jp * (16 * FROWB) + t * 32);
#pragma unroll
                for (int j = 0; j < 8; j++) mma16816(s[j], qf_hi[t], kf[j]);
#pragma unroll
                for (int j = 0; j < 8; j++) mma16816(s[j], qf_lo[t], kf[j]);
            }

            if (k0 + 63 > q0 + warp_m) {
#pragma unroll
                for (int j = 0; j < 8; j++) {
                    const int col = k0 + 8 * j + 2 * c4;
                    if (col     > row0) s[j][0] = -1e30f;
                    if (col + 1 > row0) s[j][1] = -1e30f;
                    if (col     > row1) s[j][2] = -1e30f;
                    if (col + 1 > row1) s[j][3] = -1e30f;
                }
            }

            float rx0 = -1e30f, rx1 = -1e30f;
#pragma unroll
            for (int j = 0; j < 8; j++) {
                rx0 = fmaxf(rx0, fmaxf(s[j][0], s[j][1]));
                rx1 = fmaxf(rx1, fmaxf(s[j][2], s[j][3]));
            }
            rx0 = fmaxf(rx0, __shfl_xor_sync(0xffffffffu, rx0, 1));
            rx0 = fmaxf(rx0, __shfl_xor_sync(0xffffffffu, rx0, 2));
            rx1 = fmaxf(rx1, __shfl_xor_sync(0xffffffffu, rx1, 1));
            rx1 = fmaxf(rx1, __shfl_xor_sync(0xffffffffu, rx1, 2));
            const float mn0 = fmaxf(m0, rx0), mn1 = fmaxf(m1, rx1);
            const float a0 = __expf(m0 - mn0), a1 = __expf(m1 - mn1);
            float sum0 = 0.f, sum1 = 0.f;
#pragma unroll
            for (int j = 0; j < 8; j++) {
                s[j][0] = __expf(s[j][0] - mn0);
                s[j][1] = __expf(s[j][1] - mn0);
                s[j][2] = __expf(s[j][2] - mn1);
                s[j][3] = __expf(s[j][3] - mn1);
                sum0 += s[j][0] + s[j][1];
                sum1 += s[j][2] + s[j][3];
            }
            sum0 += __shfl_xor_sync(0xffffffffu, sum0, 1);
            sum0 += __shfl_xor_sync(0xffffffffu, sum0, 2);
            sum1 += __shfl_xor_sync(0xffffffffu, sum1, 1);
            sum1 += __shfl_xor_sync(0xffffffffu, sum1, 2);
            l0 = l0 * a0 + sum0;  l1 = l1 * a1 + sum1;
            m0 = mn0;  m1 = mn1;
#pragma unroll
            for (int j = 0; j < 8; j++) {
                o[j][0] *= a0; o[j][1] *= a0; o[j][2] *= a1; o[j][3] *= a1;
            }

#pragma unroll
            for (int t = 0; t < 4; t++) {
                unsigned ahi[4], alo[4];
                {
                    const float p0 = s[2 * t][0],     p1 = s[2 * t][1];
                    const float p2 = s[2 * t][2],     p3 = s[2 * t][3];
                    const float r0 = s[2 * t + 1][0], r1 = s[2 * t + 1][1];
                    const float r2 = s[2 * t + 1][2], r3 = s[2 * t + 1][3];
                    __half h0 = __float2half_rn(p0), h1 = __float2half_rn(p1);
                    __half h2 = __float2half_rn(p2), h3 = __float2half_rn(p3);
                    __half e0 = __float2half_rn(r0), e1 = __float2half_rn(r1);
                    __half e2 = __float2half_rn(r2), e3 = __float2half_rn(r3);
                    ahi[0] = pack_h2(h0, h1); ahi[1] = pack_h2(h2, h3);
                    ahi[2] = pack_h2(e0, e1); ahi[3] = pack_h2(e2, e3);
                    alo[0] = pack_h2(__float2half_rn(p0 - __half2float(h0)),
                                     __float2half_rn(p1 - __half2float(h1)));
                    alo[1] = pack_h2(__float2half_rn(p2 - __half2float(h2)),
                                     __float2half_rn(p3 - __half2float(h3)));
                    alo[2] = pack_h2(__float2half_rn(r0 - __half2float(e0)),
                                     __float2half_rn(r1 - __half2float(e1)));
                    alo[3] = pack_h2(__float2half_rn(r2 - __half2float(e2)),
                                     __float2half_rn(r3 - __half2float(e3)));
                }
#pragma unroll
                for (int j2 = 0; j2 < 4; j2++) {
                    unsigned v0, v1, v2, v3;
                    ldsm_x4_t(v0, v1, v2, v3, va + t * (16 * FROWB) + j2 * 32);
                    unsigned bA[2] = {v0, v1}, bB[2] = {v2, v3};
                    mma16816(o[2 * j2],     ahi, bA);
                    mma16816(o[2 * j2 + 1], ahi, bB);
                    mma16816(o[2 * j2],     alo, bA);
                    mma16816(o[2 * j2 + 1], alo, bB);
                }
            }
        }
        __syncthreads();
    }

    // epilogue: normalize, split-store to g_ahi/g_alo [B,S,DM]
    const float i0 = 1.f / l0, i1 = 1.f / l1;
    const int tok0 = b * SEQ + q0 + warp_m + g;
    const int tok1 = tok0 + 8;
    const int colb = h * DH + 2 * c4;
#pragma unroll
    for (int j = 0; j < 8; j++) {
        split_store_h(g_ahi, g_alo, (size_t)tok0 * DM + colb + 8 * j,
                      o[j][0] * i0, o[j][1] * i0);
        split_store_h(g_ahi, g_alo, (size_t)tok1 * DM + colb + 8 * j,
                      o[j][2] * i1, o[j][3] * i1);
    }
}

// ---------------------------------------------------------------------------
extern "C" void kernel_launch(void* const* d_in, const int* in_sizes, int n_in,
                              void* d_out, int out_size)
{
    (void)in_sizes; (void)n_in; (void)out_size;
    const float* x    = (const float*)d_in[0];
    const float* Wqkv = (const float*)d_in[1];
    const float* bqkv = (const float*)d_in[2];
    const float* Wo   = (const float*)d_in[3];
    const float* bo   = (const float*)d_in[4];
    float* out = (float*)d_out;

    cudaFuncSetAttribute(tc_gemm_kernel<0>,
                         cudaFuncAttributeMaxDynamicSharedMemorySize, GEMM_SMEM);
    cudaFuncSetAttribute(tc_gemm_kernel<1>,
                         cudaFuncAttributeMaxDynamicSharedMemorySize, GEMM_SMEM);
    cudaFuncSetAttribute(flash_tc_kernel,
                         cudaFuncAttributeMaxDynamicSharedMemorySize, FLASH_SMEM);

    split_kernel<<<(TOKENS * DM / 4 + 255) / 256, 256>>>(x,    0, TOKENS * DM / 4);
    split_kernel<<<(3 * DM * DM / 4 + 255) / 256, 256>>>(Wqkv, 1, 3 * DM * DM / 4);
    split_kernel<<<(DM * DM / 4 + 255) / 256, 256>>>(Wo,       2, DM * DM / 4);

    tc_gemm_kernel<0><<<dim3(3 * DM / 128, TOKENS / 128), 256, GEMM_SMEM>>>(bqkv, nullptr);

    flash_tc_kernel<<<dim3(SEQ / 128, NH, BATCH), 256, FLASH_SMEM>>>();

    tc_gemm_kernel<1><<<dim3(DM / 128, TOKENS / 128), 256, GEMM_SMEM>>>(bo, out);
}

// round 9
// speedup vs baseline: 6.0404x; 1.3031x over previous
#include <cuda_runtime.h>
#include <cuda_fp16.h>
#include <math.h>

#define DM     1024
#define NH     16
#define DH     64
#define BATCH  4
#define SEQ    2048
#define TOKENS (BATCH * SEQ)

// ---------------------------------------------------------------------------
// Scratch (static device memory). fp16 mixed-precision scheme:
// x kept 2-term (hi/lo); Q, K, V, attn-out, weights single-term fp16.
// ---------------------------------------------------------------------------
__device__ __align__(16) __half g_xhi[TOKENS * DM];
__device__ __align__(16) __half g_xlo[TOKENS * DM];
__device__ __align__(16) __half g_wqkv_hi[3 * DM * DM];
__device__ __align__(16) __half g_wo_hi[DM * DM];
__device__ __align__(16) __half g_ahi[TOKENS * DM];
__device__ __align__(16) __half g_Qhi[TOKENS * DM];   // pre-scaled by 0.125
__device__ __align__(16) __half g_Khi[TOKENS * DM];
__device__ __align__(16) __half g_Vhi[TOKENS * DM];

// ---------------------------------------------------------------------------
// helpers
// ---------------------------------------------------------------------------
__device__ __forceinline__ unsigned smem_to_u32(const void* p) {
    unsigned a;
    asm("{ .reg .u64 t; cvta.to.shared.u64 t, %1; cvt.u32.u64 %0, t; }"
        : "=r"(a) : "l"(p));
    return a;
}

#define CP_ASYNC16(saddr, gptr) \
    asm volatile("cp.async.cg.shared.global [%0], [%1], 16;" \
                 :: "r"((unsigned)(saddr)), "l"(gptr))
#define CP_COMMIT() asm volatile("cp.async.commit_group;" ::: "memory")
#define CP_WAIT(n)  asm volatile("cp.async.wait_group %0;" :: "n"(n) : "memory")

__device__ __forceinline__ void ldsm_x4(unsigned& r0, unsigned& r1,
                                        unsigned& r2, unsigned& r3,
                                        unsigned addr) {
    asm volatile("ldmatrix.sync.aligned.m8n8.x4.shared.b16 {%0,%1,%2,%3}, [%4];"
                 : "=r"(r0), "=r"(r1), "=r"(r2), "=r"(r3) : "r"(addr));
}

__device__ __forceinline__ void ldsm_x4_t(unsigned& r0, unsigned& r1,
                                          unsigned& r2, unsigned& r3,
                                          unsigned addr) {
    asm volatile("ldmatrix.sync.aligned.m8n8.x4.trans.shared.b16 {%0,%1,%2,%3}, [%4];"
                 : "=r"(r0), "=r"(r1), "=r"(r2), "=r"(r3) : "r"(addr));
}

__device__ __forceinline__ void mma16816(float* d, const unsigned* a,
                                         const unsigned* b) {
    asm volatile(
        "mma.sync.aligned.m16n8k16.row.col.f32.f16.f16.f32 "
        "{%0,%1,%2,%3}, {%4,%5,%6,%7}, {%8,%9}, {%0,%1,%2,%3};"
        : "+f"(d[0]), "+f"(d[1]), "+f"(d[2]), "+f"(d[3])
        : "r"(a[0]), "r"(a[1]), "r"(a[2]), "r"(a[3]), "r"(b[0]), "r"(b[1]));
}

__device__ __forceinline__ unsigned pack_h2(__half a, __half b) {
    __half2 t = __halves2half2(a, b);
    return *(unsigned*)&t;
}

// ---------------------------------------------------------------------------
// fp32 -> fp16 conversion kernels.
// mode 0: x -> hi/lo ; mode 1: Wqkv -> hi only ; mode 2: Wo -> hi only
// ---------------------------------------------------------------------------
__global__ void __launch_bounds__(256) split_kernel(
    const float* __restrict__ src, int mode, int n4)
{
    int i = blockIdx.x * blockDim.x + threadIdx.x;
    if (i >= n4) return;
    float4 v = ((const float4*)src)[i];
    float f[4] = {v.x, v.y, v.z, v.w};
    __half h[4];
#pragma unroll
    for (int j = 0; j < 4; j++) h[j] = __float2half_rn(f[j]);

    if (mode == 0) {
        __half l[4];
#pragma unroll
        for (int j = 0; j < 4; j++)
            l[j] = __float2half_rn(f[j] - __half2float(h[j]));
        ((unsigned*)g_xhi)[2 * i]     = pack_h2(h[0], h[1]);
        ((unsigned*)g_xhi)[2 * i + 1] = pack_h2(h[2], h[3]);
        ((unsigned*)g_xlo)[2 * i]     = pack_h2(l[0], l[1]);
        ((unsigned*)g_xlo)[2 * i + 1] = pack_h2(l[2], l[3]);
    } else {
        __half* hp = (mode == 1) ? g_wqkv_hi : g_wo_hi;
        ((unsigned*)hp)[2 * i]     = pack_h2(h[0], h[1]);
        ((unsigned*)hp)[2 * i + 1] = pack_h2(h[2], h[3]);
    }
}

// ---------------------------------------------------------------------------
// Tensor-core GEMM. K=1024, CTA 128x128, 8 warps each 32x64, BK=32,
// 3-stage cp.async pipeline, one __syncthreads per chunk.
// MODE 0 (2-term A): C = (xhi+xlo)·Wqkv^T + b -> Q(fp16, scaled), K, V
// MODE 1 (1-term A): C = ahi·Wo^T + b -> fp32 Cout
// ---------------------------------------------------------------------------
#define GTILE  10240                 // 128 rows x 80B pitch
#define GSTAGE (3 * GTILE)           // Ahi|Alo|Bhi slots (Alo unused in MODE 1)
#define GEMM_SMEM (3 * GSTAGE)       // 92160 (3 stages)

template <int MODE>
__global__ void __launch_bounds__(256, 2) tc_gemm_kernel(
    const float* __restrict__ bias, float* __restrict__ Cout)
{
    extern __shared__ __align__(16) char gsm[];
    constexpr bool TWO = (MODE == 0);

    const int tid  = threadIdx.x;
    const int lane = tid & 31;
    const int wid  = tid >> 5;
    const int n0 = blockIdx.x << 7;
    const int m0 = blockIdx.y << 7;
    const int warp_m = (wid & 3) << 5;   // 0,32,64,96
    const int warp_n = (wid >> 2) << 6;  // 0,64
    const unsigned sbase = smem_to_u32(gsm);

    const __half* Ahi = (MODE == 0) ? g_xhi : g_ahi;
    const __half* Bhi = (MODE == 0) ? g_wqkv_hi : g_wo_hi;

    const int rowA = tid >> 2;
    const int quad = tid & 3;
    const __half* pA0h = Ahi + (size_t)(m0 + rowA) * DM + quad * 8;
    const __half* pA1h = pA0h + (size_t)64 * DM;
    const __half* pA0l = g_xlo + (size_t)(m0 + rowA) * DM + quad * 8;
    const __half* pA1l = pA0l + (size_t)64 * DM;
    const __half* pB0  = Bhi + (size_t)(n0 + rowA) * DM + quad * 8;
    const __half* pB1  = pB0 + (size_t)64 * DM;
    const unsigned so0 = rowA * 80 + quad * 16;
    const unsigned so1 = so0 + 64 * 80;

    const unsigned aHi0 = sbase + (warp_m + (lane & 15)) * 80 + ((lane >> 4) << 4);
    const unsigned bRow = warp_n + ((lane >> 4) << 3) + (lane & 7);
    const unsigned bHi0 = sbase + 2 * GTILE + bRow * 80 + (((lane >> 3) & 1) << 4);

    float acc[2][8][4] = {};

    // prologue: chunks 0,1 -> stages 0,1
#pragma unroll
    for (int p = 0; p < 2; p++) {
        const unsigned st = sbase + p * GSTAGE;
        const int kc = p * 32;
        CP_ASYNC16(st + so0, pA0h + kc);
        CP_ASYNC16(st + so1, pA1h + kc);
        if (TWO) {
            CP_ASYNC16(st + GTILE + so0, pA0l + kc);
            CP_ASYNC16(st + GTILE + so1, pA1l + kc);
        }
        CP_ASYNC16(st + 2 * GTILE + so0, pB0 + kc);
        CP_ASYNC16(st + 2 * GTILE + so1, pB1 + kc);
        CP_COMMIT();
    }

    int stage = 0;
    for (int c = 0; c < 32; c++) {
        if (c <= 29) { CP_WAIT(1); } else { CP_WAIT(0); }
        __syncthreads();

        const unsigned stof = (unsigned)stage * GSTAGE;
        const unsigned aHi = aHi0 + stof;
        const unsigned aLo = aHi + GTILE;
        const unsigned bHi = bHi0 + stof;

#pragma unroll
        for (int ks2 = 0; ks2 < 2; ks2++) {
            const unsigned kb = ks2 << 5;
            unsigned a_hi[2][4], a_lo[2][4], bf[8][2];
#pragma unroll
            for (int i = 0; i < 2; i++)
                ldsm_x4(a_hi[i][0], a_hi[i][1], a_hi[i][2], a_hi[i][3],
                        aHi + i * (16 * 80) + kb);
            if (TWO) {
#pragma unroll
                for (int i = 0; i < 2; i++)
                    ldsm_x4(a_lo[i][0], a_lo[i][1], a_lo[i][2], a_lo[i][3],
                            aLo + i * (16 * 80) + kb);
            }
#pragma unroll
            for (int jp = 0; jp < 4; jp++)
                ldsm_x4(bf[2 * jp][0], bf[2 * jp][1],
                        bf[2 * jp + 1][0], bf[2 * jp + 1][1],
                        bHi + jp * (16 * 80) + kb);
#pragma unroll
            for (int i = 0; i < 2; i++)
#pragma unroll
                for (int j = 0; j < 8; j++)
                    mma16816(acc[i][j], a_hi[i], bf[j]);
            if (TWO) {
#pragma unroll
                for (int i = 0; i < 2; i++)
#pragma unroll
                    for (int j = 0; j < 8; j++)
                        mma16816(acc[i][j], a_lo[i], bf[j]);
            }
        }

        if (c + 2 < 32) {
            const int ws = (stage + 2) % 3;
            const unsigned st = sbase + (unsigned)ws * GSTAGE;
            const int kc = (c + 2) * 32;
            CP_ASYNC16(st + so0, pA0h + kc);
            CP_ASYNC16(st + so1, pA1h + kc);
            if (TWO) {
                CP_ASYNC16(st + GTILE + so0, pA0l + kc);
                CP_ASYNC16(st + GTILE + so1, pA1l + kc);
            }
            CP_ASYNC16(st + 2 * GTILE + so0, pB0 + kc);
            CP_ASYNC16(st + 2 * GTILE + so1, pB1 + kc);
            CP_COMMIT();
        }
        stage = (stage + 1) % 3;
    }

    const int g = lane >> 2;
    const int c = lane & 3;
#pragma unroll
    for (int i = 0; i < 2; i++) {
#pragma unroll
        for (int j = 0; j < 8; j++) {
            const int rm = m0 + warp_m + i * 16 + g;
            const int cn = n0 + warp_n + j * 8 + 2 * c;
            const float2 bv = *(const float2*)(bias + cn);
            float v00 = acc[i][j][0] + bv.x, v01 = acc[i][j][1] + bv.y;
            float v10 = acc[i][j][2] + bv.x, v11 = acc[i][j][3] + bv.y;
            if (MODE == 0) {
                const int which = cn >> 10;           // 0=Q,1=K,2=V
                const int head  = (cn & 1023) >> 6;
                const int hcol  = cn & 63;
                const int b0r = rm >> 11, s0 = rm & 2047;
                const int b1r = (rm + 8) >> 11, s1 = (rm + 8) & 2047;
                const size_t i0 = (((size_t)(b0r * NH + head)) * SEQ + s0) * DH + hcol;
                const size_t i1 = (((size_t)(b1r * NH + head)) * SEQ + s1) * DH + hcol;
                __half* hp;
                if (which == 0) { hp = g_Qhi;
                                  v00 *= 0.125f; v01 *= 0.125f;
                                  v10 *= 0.125f; v11 *= 0.125f; }
                else if (which == 1) hp = g_Khi;
                else                 hp = g_Vhi;
                *(unsigned*)(hp + i0) =
                    pack_h2(__float2half_rn(v00), __float2half_rn(v01));
                *(unsigned*)(hp + i1) =
                    pack_h2(__float2half_rn(v10), __float2half_rn(v11));
            } else {
                *(float2*)(Cout + (size_t)rm * DM + cn) = make_float2(v00, v01);
                *(float2*)(Cout + (size_t)(rm + 8) * DM + cn) = make_float2(v10, v11);
            }
        }
    }
}

// ---------------------------------------------------------------------------
// Tensor-core causal flash attention, single-term fp16 (Q, K, V, P all fp16).
// CTA: 128 q-rows of one (b,h); 8 warps x 16 rows; K-tiles of 64.
// cp.async double-buffered Khi|Vhi tiles. Epilogue: single fp16 -> g_ahi.
// ---------------------------------------------------------------------------
#define FROWB 144
#define FTILE (64 * FROWB)          // 9216 (64-row tile)
#define FSTAGE (2 * FTILE)          // Khi|Vhi = 18432
#define FLASH_SMEM (2 * FSTAGE)     // 36864

__global__ void __launch_bounds__(256) flash_tc_kernel()
{
    extern __shared__ __align__(16) char fsm[];

    const int tid  = threadIdx.x;
    const int lane = tid & 31;
    const int wid  = tid >> 5;
    const int warp_m = wid << 4;
    const int qt = (SEQ / 128 - 1) - blockIdx.x;
    const int h  = blockIdx.y;
    const int b  = blockIdx.z;
    const int q0 = qt << 7;
    const int bh = b * NH + h;
    const size_t base = (size_t)bh * SEQ * DH;
    const unsigned sb = smem_to_u32(fsm);

    // ---- stage Q (128 rows, fp16) and extract fragments ----
    {
        const __half* qh = g_Qhi + base + (size_t)q0 * DH;
#pragma unroll
        for (int r = 0; r < 4; r++) {
            const int cc = tid + (r << 8);
            const int row = cc >> 3, ch = cc & 7;
            *(uint4*)(fsm + row * FROWB + ch * 16) =
                *(const uint4*)(qh + row * DH + ch * 8);
        }
    }
    __syncthreads();
    unsigned qf[4][4];
    {
        const unsigned qa = sb + (warp_m + (lane & 15)) * FROWB + ((lane >> 4) << 4);
#pragma unroll
        for (int t = 0; t < 4; t++)
            ldsm_x4(qf[t][0], qf[t][1], qf[t][2], qf[t][3], qa + t * 32);
    }
    __syncthreads();

    float o[8][4] = {};
    float m0 = -1e30f, m1 = -1e30f, l0 = 0.f, l1 = 0.f;
    const int g  = lane >> 2;
    const int c4 = lane & 3;
    const int row0 = q0 + warp_m + g;
    const int row1 = row0 + 8;

    const unsigned ka0 = sb + ((lane & 7) + ((lane >> 4) << 3)) * FROWB
                            + (((lane >> 3) & 1) << 4);
    const unsigned va0 = sb + FTILE
                            + ((lane & 7) + (((lane >> 3) & 1) << 3)) * FROWB
                            + ((lane >> 4) << 4);

    const int srow = tid >> 3, sch = tid & 7;
    const unsigned sso = srow * FROWB + sch * 16;
    const unsigned sgo = srow * DH + sch * 8;

    const int nkt = (q0 >> 6) + 2;

    // prologue: tile 0 -> stage 0
    {
        const __half* pk = g_Khi + base;
        const __half* pv = g_Vhi + base;
#pragma unroll
        for (int r = 0; r < 2; r++) {
            const unsigned so = sso + r * (32 * FROWB);
            const unsigned go = sgo + r * (32 * DH);
            CP_ASYNC16(sb + so, pk + go);
            CP_ASYNC16(sb + FTILE + so, pv + go);
        }
        CP_COMMIT();
    }

    for (int kt = 0; kt < nkt; kt++) {
        const int k0 = kt << 6;
        if (kt + 1 < nkt) {
            const size_t nb = base + (size_t)((kt + 1) << 6) * DH;
            const unsigned st = sb + ((kt + 1) & 1) * FSTAGE;
            const __half* pk = g_Khi + nb;
            const __half* pv = g_Vhi + nb;
#pragma unroll
            for (int r = 0; r < 2; r++) {
                const unsigned so = sso + r * (32 * FROWB);
                const unsigned go = sgo + r * (32 * DH);
                CP_ASYNC16(st + so, pk + go);
                CP_ASYNC16(st + FTILE + so, pv + go);
            }
            CP_COMMIT();
            CP_WAIT(1);
        } else {
            CP_WAIT(0);
        }
        __syncthreads();

        if (k0 <= q0 + warp_m + 15) {
            const unsigned stof = (kt & 1) * FSTAGE;
            const unsigned ka = ka0 + stof;
            const unsigned va = va0 + stof;

            float s[8][4];
#pragma unroll
            for (int j = 0; j < 8; j++)
#pragma unroll
                for (int x = 0; x < 4; x++) s[j][x] = 0.f;

#pragma unroll
            for (int t = 0; t < 4; t++) {
                unsigned kf[8][2];
#pragma unroll
                for (int jp = 0; jp < 4; jp++)
                    ldsm_x4(kf[2 * jp][0], kf[2 * jp][1],
                            kf[2 * jp + 1][0], kf[2 * jp + 1][1],
                            ka + jp * (16 * FROWB) + t * 32);
#pragma unroll
                for (int j = 0; j < 8; j++) mma16816(s[j], qf[t], kf[j]);
            }

            if (k0 + 63 > q0 + warp_m) {
#pragma unroll
                for (int j = 0; j < 8; j++) {
                    const int col = k0 + 8 * j + 2 * c4;
                    if (col     > row0) s[j][0] = -1e30f;
                    if (col + 1 > row0) s[j][1] = -1e30f;
                    if (col     > row1) s[j][2] = -1e30f;
                    if (col + 1 > row1) s[j][3] = -1e30f;
                }
            }

            float rx0 = -1e30f, rx1 = -1e30f;
#pragma unroll
            for (int j = 0; j < 8; j++) {
                rx0 = fmaxf(rx0, fmaxf(s[j][0], s[j][1]));
                rx1 = fmaxf(rx1, fmaxf(s[j][2], s[j][3]));
            }
            rx0 = fmaxf(rx0, __shfl_xor_sync(0xffffffffu, rx0, 1));
            rx0 = fmaxf(rx0, __shfl_xor_sync(0xffffffffu, rx0, 2));
            rx1 = fmaxf(rx1, __shfl_xor_sync(0xffffffffu, rx1, 1));
            rx1 = fmaxf(rx1, __shfl_xor_sync(0xffffffffu, rx1, 2));
            const float mn0 = fmaxf(m0, rx0), mn1 = fmaxf(m1, rx1);
            const float a0 = __expf(m0 - mn0), a1 = __expf(m1 - mn1);
            float sum0 = 0.f, sum1 = 0.f;
#pragma unroll
            for (int j = 0; j < 8; j++) {
                s[j][0] = __expf(s[j][0] - mn0);
                s[j][1] = __expf(s[j][1] - mn0);
                s[j][2] = __expf(s[j][2] - mn1);
                s[j][3] = __expf(s[j][3] - mn1);
                sum0 += s[j][0] + s[j][1];
                sum1 += s[j][2] + s[j][3];
            }
            sum0 += __shfl_xor_sync(0xffffffffu, sum0, 1);
            sum0 += __shfl_xor_sync(0xffffffffu, sum0, 2);
            sum1 += __shfl_xor_sync(0xffffffffu, sum1, 1);
            sum1 += __shfl_xor_sync(0xffffffffu, sum1, 2);
            l0 = l0 * a0 + sum0;  l1 = l1 * a1 + sum1;
            m0 = mn0;  m1 = mn1;
#pragma unroll
            for (int j = 0; j < 8; j++) {
                o[j][0] *= a0; o[j][1] *= a0; o[j][2] *= a1; o[j][3] *= a1;
            }

#pragma unroll
            for (int t = 0; t < 4; t++) {
                unsigned ahi[4];
                ahi[0] = pack_h2(__float2half_rn(s[2 * t][0]),
                                 __float2half_rn(s[2 * t][1]));
                ahi[1] = pack_h2(__float2half_rn(s[2 * t][2]),
                                 __float2half_rn(s[2 * t][3]));
                ahi[2] = pack_h2(__float2half_rn(s[2 * t + 1][0]),
                                 __float2half_rn(s[2 * t + 1][1]));
                ahi[3] = pack_h2(__float2half_rn(s[2 * t + 1][2]),
                                 __float2half_rn(s[2 * t + 1][3]));
#pragma unroll
                for (int j2 = 0; j2 < 4; j2++) {
                    unsigned v0, v1, v2, v3;
                    ldsm_x4_t(v0, v1, v2, v3, va + t * (16 * FROWB) + j2 * 32);
                    unsigned bA[2] = {v0, v1}, bB[2] = {v2, v3};
                    mma16816(o[2 * j2],     ahi, bA);
                    mma16816(o[2 * j2 + 1], ahi, bB);
                }
            }
        }
        __syncthreads();
    }

    // epilogue: normalize, single fp16 store to g_ahi [B,S,DM]
    const float i0 = 1.f / l0, i1 = 1.f / l1;
    const int tok0 = b * SEQ + q0 + warp_m + g;
    const int tok1 = tok0 + 8;
    const int colb = h * DH + 2 * c4;
#pragma unroll
    for (int j = 0; j < 8; j++) {
        *(unsigned*)(g_ahi + (size_t)tok0 * DM + colb + 8 * j) =
            pack_h2(__float2half_rn(o[j][0] * i0), __float2half_rn(o[j][1] * i0));
        *(unsigned*)(g_ahi + (size_t)tok1 * DM + colb + 8 * j) =
            pack_h2(__float2half_rn(o[j][2] * i1), __float2half_rn(o[j][3] * i1));
    }
}

// ---------------------------------------------------------------------------
extern "C" void kernel_launch(void* const* d_in, const int* in_sizes, int n_in,
                              void* d_out, int out_size)
{
    (void)in_sizes; (void)n_in; (void)out_size;
    const float* x    = (const float*)d_in[0];
    const float* Wqkv = (const float*)d_in[1];
    const float* bqkv = (const float*)d_in[2];
    const float* Wo   = (const float*)d_in[3];
    const float* bo   = (const float*)d_in[4];
    float* out = (float*)d_out;

    cudaFuncSetAttribute(tc_gemm_kernel<0>,
                         cudaFuncAttributeMaxDynamicSharedMemorySize, GEMM_SMEM);
    cudaFuncSetAttribute(tc_gemm_kernel<1>,
                         cudaFuncAttributeMaxDynamicSharedMemorySize, GEMM_SMEM);
    cudaFuncSetAttribute(flash_tc_kernel,
                         cudaFuncAttributeMaxDynamicSharedMemorySize, FLASH_SMEM);

    split_kernel<<<(TOKENS * DM / 4 + 255) / 256, 256>>>(x,    0, TOKENS * DM / 4);
    split_kernel<<<(3 * DM * DM / 4 + 255) / 256, 256>>>(Wqkv, 1, 3 * DM * DM / 4);
    split_kernel<<<(DM * DM / 4 + 255) / 256, 256>>>(Wo,       2, DM * DM / 4);

    tc_gemm_kernel<0><<<dim3(3 * DM / 128, TOKENS / 128), 256, GEMM_SMEM>>>(bqkv, nullptr);

    flash_tc_kernel<<<dim3(SEQ / 128, NH, BATCH), 256, FLASH_SMEM>>>();

    tc_gemm_kernel<1><<<dim3(DM / 128, TOKENS / 128), 256, GEMM_SMEM>>>(bo, out);
}

// round 10
// speedup vs baseline: 7.4432x; 1.2322x over previous
#include <cuda_runtime.h>
#include <cuda_fp16.h>
#include <math.h>

#define DM     1024
#define NH     16
#define DH     64
#define BATCH  4
#define SEQ    2048
#define TOKENS (BATCH * SEQ)

// ---------------------------------------------------------------------------
// Scratch (static device memory). Fully single-term fp16 scheme.
// ---------------------------------------------------------------------------
__device__ __align__(16) __half g_xhi[TOKENS * DM];
__device__ __align__(16) __half g_wqkv_hi[3 * DM * DM];
__device__ __align__(16) __half g_wo_hi[DM * DM];
__device__ __align__(16) __half g_ahi[TOKENS * DM];
__device__ __align__(16) __half g_Qhi[TOKENS * DM];   // pre-scaled by 0.125
__device__ __align__(16) __half g_Khi[TOKENS * DM];
__device__ __align__(16) __half g_Vhi[TOKENS * DM];

// ---------------------------------------------------------------------------
// helpers
// ---------------------------------------------------------------------------
__device__ __forceinline__ unsigned smem_to_u32(const void* p) {
    unsigned a;
    asm("{ .reg .u64 t; cvta.to.shared.u64 t, %1; cvt.u32.u64 %0, t; }"
        : "=r"(a) : "l"(p));
    return a;
}

#define CP_ASYNC16(saddr, gptr) \
    asm volatile("cp.async.cg.shared.global [%0], [%1], 16;" \
                 :: "r"((unsigned)(saddr)), "l"(gptr))
#define CP_COMMIT() asm volatile("cp.async.commit_group;" ::: "memory")
#define CP_WAIT(n)  asm volatile("cp.async.wait_group %0;" :: "n"(n) : "memory")

__device__ __forceinline__ void ldsm_x4(unsigned& r0, unsigned& r1,
                                        unsigned& r2, unsigned& r3,
                                        unsigned addr) {
    asm volatile("ldmatrix.sync.aligned.m8n8.x4.shared.b16 {%0,%1,%2,%3}, [%4];"
                 : "=r"(r0), "=r"(r1), "=r"(r2), "=r"(r3) : "r"(addr));
}

__device__ __forceinline__ void ldsm_x4_t(unsigned& r0, unsigned& r1,
                                          unsigned& r2, unsigned& r3,
                                          unsigned addr) {
    asm volatile("ldmatrix.sync.aligned.m8n8.x4.trans.shared.b16 {%0,%1,%2,%3}, [%4];"
                 : "=r"(r0), "=r"(r1), "=r"(r2), "=r"(r3) : "r"(addr));
}

__device__ __forceinline__ void mma16816(float* d, const unsigned* a,
                                         const unsigned* b) {
    asm volatile(
        "mma.sync.aligned.m16n8k16.row.col.f32.f16.f16.f32 "
        "{%0,%1,%2,%3}, {%4,%5,%6,%7}, {%8,%9}, {%0,%1,%2,%3};"
        : "+f"(d[0]), "+f"(d[1]), "+f"(d[2]), "+f"(d[3])
        : "r"(a[0]), "r"(a[1]), "r"(a[2]), "r"(a[3]), "r"(b[0]), "r"(b[1]));
}

__device__ __forceinline__ unsigned pack_h2(__half a, __half b) {
    __half2 t = __halves2half2(a, b);
    return *(unsigned*)&t;
}

// ---------------------------------------------------------------------------
// fp32 -> fp16 convert. mode 0: x ; mode 1: Wqkv ; mode 2: Wo
// ---------------------------------------------------------------------------
__global__ void __launch_bounds__(256) split_kernel(
    const float* __restrict__ src, int mode, int n4)
{
    int i = blockIdx.x * blockDim.x + threadIdx.x;
    if (i >= n4) return;
    float4 v = ((const float4*)src)[i];
    __half* hp = (mode == 0) ? g_xhi : (mode == 1) ? g_wqkv_hi : g_wo_hi;
    ((unsigned*)hp)[2 * i] =
        pack_h2(__float2half_rn(v.x), __float2half_rn(v.y));
    ((unsigned*)hp)[2 * i + 1] =
        pack_h2(__float2half_rn(v.z), __float2half_rn(v.w));
}

// ---------------------------------------------------------------------------
// Tensor-core GEMM, single-term fp16: C = A·B^T + bias. K=1024.
// CTA 128x128, 8 warps each 32x64, BK=32, 3-stage cp.async, one sync/chunk.
// MODE 0: A=xhi, B=Wqkv -> Q(fp16, scaled 0.125), K, V in [B,H,S,DH]
// MODE 1: A=ahi, B=Wo  -> fp32 row-major Cout
// ---------------------------------------------------------------------------
#define GTILE  10240                 // 128 rows x 80B pitch
#define GSTAGE (2 * GTILE)           // A|B = 20480
#define GEMM_SMEM (3 * GSTAGE)       // 61440 (3 stages)

template <int MODE>
__global__ void __launch_bounds__(256, 2) tc_gemm_kernel(
    const float* __restrict__ bias, float* __restrict__ Cout)
{
    extern __shared__ __align__(16) char gsm[];

    const int tid  = threadIdx.x;
    const int lane = tid & 31;
    const int wid  = tid >> 5;
    const int n0 = blockIdx.x << 7;
    const int m0 = blockIdx.y << 7;
    const int warp_m = (wid & 3) << 5;   // 0,32,64,96
    const int warp_n = (wid >> 2) << 6;  // 0,64
    const unsigned sbase = smem_to_u32(gsm);

    const __half* Ahi = (MODE == 0) ? g_xhi : g_ahi;
    const __half* Bhi = (MODE == 0) ? g_wqkv_hi : g_wo_hi;

    const int rowA = tid >> 2;
    const int quad = tid & 3;
    const __half* pA0 = Ahi + (size_t)(m0 + rowA) * DM + quad * 8;
    const __half* pA1 = pA0 + (size_t)64 * DM;
    const __half* pB0 = Bhi + (size_t)(n0 + rowA) * DM + quad * 8;
    const __half* pB1 = pB0 + (size_t)64 * DM;
    const unsigned so0 = rowA * 80 + quad * 16;
    const unsigned so1 = so0 + 64 * 80;

    const unsigned aHi0 = sbase + (warp_m + (lane & 15)) * 80 + ((lane >> 4) << 4);
    const unsigned bRow = warp_n + ((lane >> 4) << 3) + (lane & 7);
    const unsigned bHi0 = sbase + GTILE + bRow * 80 + (((lane >> 3) & 1) << 4);

    float acc[2][8][4] = {};

    // prologue: chunks 0,1 -> stages 0,1
#pragma unroll
    for (int p = 0; p < 2; p++) {
        const unsigned st = sbase + p * GSTAGE;
        const int kc = p * 32;
        CP_ASYNC16(st + so0, pA0 + kc);
        CP_ASYNC16(st + so1, pA1 + kc);
        CP_ASYNC16(st + GTILE + so0, pB0 + kc);
        CP_ASYNC16(st + GTILE + so1, pB1 + kc);
        CP_COMMIT();
    }

    int stage = 0;
    for (int c = 0; c < 32; c++) {
        if (c <= 29) { CP_WAIT(1); } else { CP_WAIT(0); }
        __syncthreads();

        const unsigned stof = (unsigned)stage * GSTAGE;
        const unsigned aHi = aHi0 + stof;
        const unsigned bHi = bHi0 + stof;

#pragma unroll
        for (int ks2 = 0; ks2 < 2; ks2++) {
            const unsigned kb = ks2 << 5;
            unsigned a_hi[2][4], bf[8][2];
#pragma unroll
            for (int i = 0; i < 2; i++)
                ldsm_x4(a_hi[i][0], a_hi[i][1], a_hi[i][2], a_hi[i][3],
                        aHi + i * (16 * 80) + kb);
#pragma unroll
            for (int jp = 0; jp < 4; jp++)
                ldsm_x4(bf[2 * jp][0], bf[2 * jp][1],
                        bf[2 * jp + 1][0], bf[2 * jp + 1][1],
                        bHi + jp * (16 * 80) + kb);
#pragma unroll
            for (int i = 0; i < 2; i++)
#pragma unroll
                for (int j = 0; j < 8; j++)
                    mma16816(acc[i][j], a_hi[i], bf[j]);
        }

        if (c + 2 < 32) {
            const int ws = (stage + 2) % 3;
            const unsigned st = sbase + (unsigned)ws * GSTAGE;
            const int kc = (c + 2) * 32;
            CP_ASYNC16(st + so0, pA0 + kc);
            CP_ASYNC16(st + so1, pA1 + kc);
            CP_ASYNC16(st + GTILE + so0, pB0 + kc);
            CP_ASYNC16(st + GTILE + so1, pB1 + kc);
            CP_COMMIT();
        }
        stage = (stage + 1) % 3;
    }

    const int g = lane >> 2;
    const int c = lane & 3;
#pragma unroll
    for (int i = 0; i < 2; i++) {
#pragma unroll
        for (int j = 0; j < 8; j++) {
            const int rm = m0 + warp_m + i * 16 + g;
            const int cn = n0 + warp_n + j * 8 + 2 * c;
            const float2 bv = *(const float2*)(bias + cn);
            float v00 = acc[i][j][0] + bv.x, v01 = acc[i][j][1] + bv.y;
            float v10 = acc[i][j][2] + bv.x, v11 = acc[i][j][3] + bv.y;
            if (MODE == 0) {
                const int which = cn >> 10;           // 0=Q,1=K,2=V
                const int head  = (cn & 1023) >> 6;
                const int hcol  = cn & 63;
                const int b0r = rm >> 11, s0 = rm & 2047;
                const int b1r = (rm + 8) >> 11, s1 = (rm + 8) & 2047;
                const size_t i0 = (((size_t)(b0r * NH + head)) * SEQ + s0) * DH + hcol;
                const size_t i1 = (((size_t)(b1r * NH + head)) * SEQ + s1) * DH + hcol;
                __half* hp;
                if (which == 0) { hp = g_Qhi;
                                  v00 *= 0.125f; v01 *= 0.125f;
                                  v10 *= 0.125f; v11 *= 0.125f; }
                else if (which == 1) hp = g_Khi;
                else                 hp = g_Vhi;
                *(unsigned*)(hp + i0) =
                    pack_h2(__float2half_rn(v00), __float2half_rn(v01));
                *(unsigned*)(hp + i1) =
                    pack_h2(__float2half_rn(v10), __float2half_rn(v11));
            } else {
                *(float2*)(Cout + (size_t)rm * DM + cn) = make_float2(v00, v01);
                *(float2*)(Cout + (size_t)(rm + 8) * DM + cn) = make_float2(v10, v11);
            }
        }
    }
}

// ---------------------------------------------------------------------------
// Tensor-core causal flash attention, single-term fp16 (unchanged from R9).
// ---------------------------------------------------------------------------
#define FROWB 144
#define FTILE (64 * FROWB)          // 9216 (64-row tile)
#define FSTAGE (2 * FTILE)          // Khi|Vhi = 18432
#define FLASH_SMEM (2 * FSTAGE)     // 36864

__global__ void __launch_bounds__(256) flash_tc_kernel()
{
    extern __shared__ __align__(16) char fsm[];

    const int tid  = threadIdx.x;
    const int lane = tid & 31;
    const int wid  = tid >> 5;
    const int warp_m = wid << 4;
    const int qt = (SEQ / 128 - 1) - blockIdx.x;
    const int h  = blockIdx.y;
    const int b  = blockIdx.z;
    const int q0 = qt << 7;
    const int bh = b * NH + h;
    const size_t base = (size_t)bh * SEQ * DH;
    const unsigned sb = smem_to_u32(fsm);

    // ---- stage Q (128 rows, fp16) and extract fragments ----
    {
        const __half* qh = g_Qhi + base + (size_t)q0 * DH;
#pragma unroll
        for (int r = 0; r < 4; r++) {
            const int cc = tid + (r << 8);
            const int row = cc >> 3, ch = cc & 7;
            *(uint4*)(fsm + row * FROWB + ch * 16) =
                *(const uint4*)(qh + row * DH + ch * 8);
        }
    }
    __syncthreads();
    unsigned qf[4][4];
    {
        const unsigned qa = sb + (warp_m + (lane & 15)) * FROWB + ((lane >> 4) << 4);
#pragma unroll
        for (int t = 0; t < 4; t++)
            ldsm_x4(qf[t][0], qf[t][1], qf[t][2], qf[t][3], qa + t * 32);
    }
    __syncthreads();

    float o[8][4] = {};
    float m0 = -1e30f, m1 = -1e30f, l0 = 0.f, l1 = 0.f;
    const int g  = lane >> 2;
    const int c4 = lane & 3;
    const int row0 = q0 + warp_m + g;
    const int row1 = row0 + 8;

    const unsigned ka0 = sb + ((lane & 7) + ((lane >> 4) << 3)) * FROWB
                            + (((lane >> 3) & 1) << 4);
    const unsigned va0 = sb + FTILE
                            + ((lane & 7) + (((lane >> 3) & 1) << 3)) * FROWB
                            + ((lane >> 4) << 4);

    const int srow = tid >> 3, sch = tid & 7;
    const unsigned sso = srow * FROWB + sch * 16;
    const unsigned sgo = srow * DH + sch * 8;

    const int nkt = (q0 >> 6) + 2;

    // prologue: tile 0 -> stage 0
    {
        const __half* pk = g_Khi + base;
        const __half* pv = g_Vhi + base;
#pragma unroll
        for (int r = 0; r < 2; r++) {
            const unsigned so = sso + r * (32 * FROWB);
            const unsigned go = sgo + r * (32 * DH);
            CP_ASYNC16(sb + so, pk + go);
            CP_ASYNC16(sb + FTILE + so, pv + go);
        }
        CP_COMMIT();
    }

    for (int kt = 0; kt < nkt; kt++) {
        const int k0 = kt << 6;
        if (kt + 1 < nkt) {
            const size_t nb = base + (size_t)((kt + 1) << 6) * DH;
            const unsigned st = sb + ((kt + 1) & 1) * FSTAGE;
            const __half* pk = g_Khi + nb;
            const __half* pv = g_Vhi + nb;
#pragma unroll
            for (int r = 0; r < 2; r++) {
                const unsigned so = sso + r * (32 * FROWB);
                const unsigned go = sgo + r * (32 * DH);
                CP_ASYNC16(st + so, pk + go);
                CP_ASYNC16(st + FTILE + so, pv + go);
            }
            CP_COMMIT();
            CP_WAIT(1);
        } else {
            CP_WAIT(0);
        }
        __syncthreads();

        if (k0 <= q0 + warp_m + 15) {
            const unsigned stof = (kt & 1) * FSTAGE;
            const unsigned ka = ka0 + stof;
            const unsigned va = va0 + stof;

            float s[8][4];
#pragma unroll
            for (int j = 0; j < 8; j++)
#pragma unroll
                for (int x = 0; x < 4; x++) s[j][x] = 0.f;

#pragma unroll
            for (int t = 0; t < 4; t++) {
                unsigned kf[8][2];
#pragma unroll
                for (int jp = 0; jp < 4; jp++)
                    ldsm_x4(kf[2 * jp][0], kf[2 * jp][1],
                            kf[2 * jp + 1][0], kf[2 * jp + 1][1],
                            ka + jp * (16 * FROWB) + t * 32);
#pragma unroll
                for (int j = 0; j < 8; j++) mma16816(s[j], qf[t], kf[j]);
            }

            if (k0 + 63 > q0 + warp_m) {
#pragma unroll
                for (int j = 0; j < 8; j++) {
                    const int col = k0 + 8 * j + 2 * c4;
                    if (col     > row0) s[j][0] = -1e30f;
                    if (col + 1 > row0) s[j][1] = -1e30f;
                    if (col     > row1) s[j][2] = -1e30f;
                    if (col + 1 > row1) s[j][3] = -1e30f;
                }
            }

            float rx0 = -1e30f, rx1 = -1e30f;
#pragma unroll
            for (int j = 0; j < 8; j++) {
                rx0 = fmaxf(rx0, fmaxf(s[j][0], s[j][1]));
                rx1 = fmaxf(rx1, fmaxf(s[j][2], s[j][3]));
            }
            rx0 = fmaxf(rx0, __shfl_xor_sync(0xffffffffu, rx0, 1));
            rx0 = fmaxf(rx0, __shfl_xor_sync(0xffffffffu, rx0, 2));
            rx1 = fmaxf(rx1, __shfl_xor_sync(0xffffffffu, rx1, 1));
            rx1 = fmaxf(rx1, __shfl_xor_sync(0xffffffffu, rx1, 2));
            const float mn0 = fmaxf(m0, rx0), mn1 = fmaxf(m1, rx1);
            const float a0 = __expf(m0 - mn0), a1 = __expf(m1 - mn1);
            float sum0 = 0.f, sum1 = 0.f;
#pragma unroll
            for (int j = 0; j < 8; j++) {
                s[j][0] = __expf(s[j][0] - mn0);
                s[j][1] = __expf(s[j][1] - mn0);
                s[j][2] = __expf(s[j][2] - mn1);
                s[j][3] = __expf(s[j][3] - mn1);
                sum0 += s[j][0] + s[j][1];
                sum1 += s[j][2] + s[j][3];
            }
            sum0 += __shfl_xor_sync(0xffffffffu, sum0, 1);
            sum0 += __shfl_xor_sync(0xffffffffu, sum0, 2);
            sum1 += __shfl_xor_sync(0xffffffffu, sum1, 1);
            sum1 += __shfl_xor_sync(0xffffffffu, sum1, 2);
            l0 = l0 * a0 + sum0;  l1 = l1 * a1 + sum1;
            m0 = mn0;  m1 = mn1;
#pragma unroll
            for (int j = 0; j < 8; j++) {
                o[j][0] *= a0; o[j][1] *= a0; o[j][2] *= a1; o[j][3] *= a1;
            }

#pragma unroll
            for (int t = 0; t < 4; t++) {
                unsigned ahi[4];
                ahi[0] = pack_h2(__float2half_rn(s[2 * t][0]),
                                 __float2half_rn(s[2 * t][1]));
                ahi[1] = pack_h2(__float2half_rn(s[2 * t][2]),
                                 __float2half_rn(s[2 * t][3]));
                ahi[2] = pack_h2(__float2half_rn(s[2 * t + 1][0]),
                                 __float2half_rn(s[2 * t + 1][1]));
                ahi[3] = pack_h2(__float2half_rn(s[2 * t + 1][2]),
                                 __float2half_rn(s[2 * t + 1][3]));
#pragma unroll
                for (int j2 = 0; j2 < 4; j2++) {
                    unsigned v0, v1, v2, v3;
                    ldsm_x4_t(v0, v1, v2, v3, va + t * (16 * FROWB) + j2 * 32);
                    unsigned bA[2] = {v0, v1}, bB[2] = {v2, v3};
                    mma16816(o[2 * j2],     ahi, bA);
                    mma16816(o[2 * j2 + 1], ahi, bB);
                }
            }
        }
        __syncthreads();
    }

    // epilogue: normalize, single fp16 store to g_ahi [B,S,DM]
    const float i0 = 1.f / l0, i1 = 1.f / l1;
    const int tok0 = b * SEQ + q0 + warp_m + g;
    const int tok1 = tok0 + 8;
    const int colb = h * DH + 2 * c4;
#pragma unroll
    for (int j = 0; j < 8; j++) {
        *(unsigned*)(g_ahi + (size_t)tok0 * DM + colb + 8 * j) =
            pack_h2(__float2half_rn(o[j][0] * i0), __float2half_rn(o[j][1] * i0));
        *(unsigned*)(g_ahi + (size_t)tok1 * DM + colb + 8 * j) =
            pack_h2(__float2half_rn(o[j][2] * i1), __float2half_rn(o[j][3] * i1));
    }
}

// ---------------------------------------------------------------------------
extern "C" void kernel_launch(void* const* d_in, const int* in_sizes, int n_in,
                              void* d_out, int out_size)
{
    (void)in_sizes; (void)n_in; (void)out_size;
    const float* x    = (const float*)d_in[0];
    const float* Wqkv = (const float*)d_in[1];
    const float* bqkv = (const float*)d_in[2];
    const float* Wo   = (const float*)d_in[3];
    const float* bo   = (const float*)d_in[4];
    float* out = (float*)d_out;

    cudaFuncSetAttribute(tc_gemm_kernel<0>,
                         cudaFuncAttributeMaxDynamicSharedMemorySize, GEMM_SMEM);
    cudaFuncSetAttribute(tc_gemm_kernel<1>,
                         cudaFuncAttributeMaxDynamicSharedMemorySize, GEMM_SMEM);
    cudaFuncSetAttribute(flash_tc_kernel,
                         cudaFuncAttributeMaxDynamicSharedMemorySize, FLASH_SMEM);

    split_kernel<<<(TOKENS * DM / 4 + 255) / 256, 256>>>(x,    0, TOKENS * DM / 4);
    split_kernel<<<(3 * DM * DM / 4 + 255) / 256, 256>>>(Wqkv, 1, 3 * DM * DM / 4);
    split_kernel<<<(DM * DM / 4 + 255) / 256, 256>>>(Wo,       2, DM * DM / 4);

    tc_gemm_kernel<0><<<dim3(3 * DM / 128, TOKENS / 128), 256, GEMM_SMEM>>>(bqkv, nullptr);

    flash_tc_kernel<<<dim3(SEQ / 128, NH, BATCH), 256, FLASH_SMEM>>>();

    tc_gemm_kernel<1><<<dim3(DM / 128, TOKENS / 128), 256, GEMM_SMEM>>>(bo, out);
}